// round 12
// baseline (speedup 1.0000x reference)
#include <cuda_runtime.h>
#include <math.h>

// Problem constants
#define Bn   4
#define Sn   2048
#define Dn   1024
#define Mrows (Bn*Sn)          // 8192
#define K2   (2*Dn)            // 2048
#define BSD  (Bn*Sn*Dn)        // 8388608
#define GAMMA 0.01f
#define COND_TH 100.0f

// ---------------- scratch (device globals; allocation-free) ----------------
__device__ float g_psi [Mrows * K2];          // [8192, 2048]  [Re | Im]
__device__ float g_am  [Mrows * Dn];          // dual-use: A3 = Ar+Ai, then mag (tf32-rounded)
__device__ float g_T   [3 * Mrows * Dn];      // T1, T2, T3  (each [8192,1024])
__device__ float g_B3  [2 * 3 * Dn * Dn];     // per layer: B1=Wr-I, B2=Wi, B3=B1+B2 (tf32-rounded)
__device__ float g_H   [2 * Bn * Dn * Dn];    // per-layer [B, D, D]
__device__ float g_dampf[2 * Dn];             // (1 - gamma*sum L^2)
// [0]=sumsq, [4..7]=diffsq[b], [8..11]=prevsq[b],
// [12..15]=dmax[b], [16..19]=dmin[b], [20..23]=cr[b], [24..27]=ci[b]
__device__ float g_scal[32];

__device__ __forceinline__ unsigned f2tf(float f)
{
    unsigned r;
    asm("cvt.rna.tf32.f32 %0, %1;" : "=r"(r) : "f"(f));
    return r;
}
__device__ __forceinline__ float f2tf_f(float f) { unsigned r = f2tf(f); return __uint_as_float(r); }

__device__ __forceinline__ void mma8(float* c, const unsigned* a, const unsigned* b)
{
    asm("mma.sync.aligned.m16n8k8.row.col.f32.tf32.tf32.f32 "
        "{%0,%1,%2,%3}, {%4,%5,%6,%7}, {%8,%9}, {%0,%1,%2,%3};"
        : "+f"(c[0]), "+f"(c[1]), "+f"(c[2]), "+f"(c[3])
        : "r"(a[0]), "r"(a[1]), "r"(a[2]), "r"(a[3]), "r"(b[0]), "r"(b[1]));
}

// ---------------- prep kernels ----------------
// B1 = Wr - I, B2 = Wi, B3 = B1 + B2, all [k][n] per layer, tf32-pre-rounded
__global__ void k_buildB3(const float* __restrict__ Wr, const float* __restrict__ Wi)
{
    int i = blockIdx.x * 256 + threadIdx.x;       // 2 * 1024 * 1024
    int l = i >> 20;
    int kn = i & 1048575;
    int k = kn >> 10, n = kn & 1023;
    size_t WL = (size_t)l * Dn * Dn + kn;
    float b1 = Wr[WL] - (k == n ? 1.0f : 0.0f);
    float b2 = Wi[WL];
    size_t base = (size_t)l * 3 * Dn * Dn + kn;
    g_B3[base]               = f2tf_f(b1);
    g_B3[base + Dn * Dn]     = f2tf_f(b2);
    g_B3[base + 2 * Dn * Dn] = f2tf_f(b1 + b2);
}

__global__ void k_damp(const float* __restrict__ L)
{
    int t = blockIdx.x * 256 + threadIdx.x;   // 2048
    if (t < 2 * Dn) {
        int l = t >> 10, d = t & 1023;
        float s = 0.f;
        #pragma unroll
        for (int k = 0; k < 4; k++) { float v = L[l * 4096 + k * Dn + d]; s += v * v; }
        g_dampf[t] = 1.0f - GAMMA * s;
    }
}

__global__ void k_init_scal()
{
    int t = threadIdx.x;
    if (t < 32) g_scal[t] = (t >= 16 && t < 20) ? __int_as_float(0x7f800000) : 0.0f;
}

__global__ void k_pack(const float* __restrict__ xr, const float* __restrict__ xi)
{
    int i = blockIdx.x * 256 + threadIdx.x;   // BSD/4
    int m = i >> 8, dq = i & 255;
    float4 r = *(const float4*)&xr[m * Dn + dq * 4];
    float4 im = *(const float4*)&xi[m * Dn + dq * 4];
    *(float4*)&g_psi[m * K2 + dq * 4]      = r;
    *(float4*)&g_psi[m * K2 + Dn + dq * 4] = im;
    float4 a3;
    a3.x = f2tf_f(r.x + im.x); a3.y = f2tf_f(r.y + im.y);
    a3.z = f2tf_f(r.z + im.z); a3.w = f2tf_f(r.w + im.w);
    *(float4*)&g_am[m * Dn + dq * 4] = a3;
}

// ---------------- Karatsuba T GEMMs (TF32 MMA): T_z = A_z @ B_z, K=1024 ----------
// Double-buffered smem, one __syncthreads per K-tile.
#define KT 16
#define SP 136    // smem row stride: 136 % 32 == 8 -> conflict-free fragment loads

__global__ __launch_bounds__(256, 2) void k_gemmT(int layer)
{
    const int z = blockIdx.z;
    const float* __restrict__ A = (z == 0) ? g_psi : (z == 1) ? (g_psi + Dn) : g_am;
    const int lda = (z == 2) ? Dn : K2;
    const bool cvtA = (z != 2);               // z=2 (A3) is pre-rounded
    const float* __restrict__ Bm = g_B3 + ((size_t)layer * 3 + z) * Dn * Dn;
    float* __restrict__ C = g_T + (size_t)z * Mrows * Dn;

    __shared__ unsigned As[2][KT][SP];   // As[buf][k][m]
    __shared__ unsigned Bs[2][KT][SP];   // Bs[buf][k][n]

    const int tid = threadIdx.x;
    const int m0 = blockIdx.y * 128;
    const int n0 = blockIdx.x * 128;
    const int lane = tid & 31, wid = tid >> 5;
    const int wm = (wid >> 2) * 64;
    const int wn = (wid & 3) * 32;
    const int g = lane >> 2, tig = lane & 3;

    float acc[4][4][4];
    #pragma unroll
    for (int i = 0; i < 4; i++)
        #pragma unroll
        for (int j = 0; j < 4; j++)
            #pragma unroll
            for (int k = 0; k < 4; k++) acc[i][j][k] = 0.f;

    int buf = 0;
    for (int kt = 0; kt < Dn; kt += KT, buf ^= 1) {
        // stage tile kt into buf
        #pragma unroll
        for (int u = 0; u < 2; u++) {
            int idx = tid + u * 256;
            int ar = idx >> 2, kq = idx & 3;
            float4 va = *(const float4*)&A[(size_t)(m0 + ar) * lda + kt + kq * 4];
            if (cvtA) {
                As[buf][kq * 4 + 0][ar] = f2tf(va.x);
                As[buf][kq * 4 + 1][ar] = f2tf(va.y);
                As[buf][kq * 4 + 2][ar] = f2tf(va.z);
                As[buf][kq * 4 + 3][ar] = f2tf(va.w);
            } else {
                As[buf][kq * 4 + 0][ar] = __float_as_uint(va.x);
                As[buf][kq * 4 + 1][ar] = __float_as_uint(va.y);
                As[buf][kq * 4 + 2][ar] = __float_as_uint(va.z);
                As[buf][kq * 4 + 3][ar] = __float_as_uint(va.w);
            }
            int br = idx >> 5, bq = idx & 31;
            float4 vb = *(const float4*)&Bm[(size_t)(kt + br) * Dn + n0 + bq * 4];
            uint4 v;
            v.x = __float_as_uint(vb.x); v.y = __float_as_uint(vb.y);
            v.z = __float_as_uint(vb.z); v.w = __float_as_uint(vb.w);
            *(uint4*)&Bs[buf][br][bq * 4] = v;
        }
        __syncthreads();
        // mma from buf (other warps may already stage next tile into buf^1)
        #pragma unroll
        for (int kb = 0; kb < KT; kb += 8) {
            unsigned afr[4][4], bfr[4][2];
            #pragma unroll
            for (int am = 0; am < 4; am++) {
                int m = wm + am * 16 + g;
                afr[am][0] = As[buf][kb + tig][m];
                afr[am][1] = As[buf][kb + tig][m + 8];
                afr[am][2] = As[buf][kb + tig + 4][m];
                afr[am][3] = As[buf][kb + tig + 4][m + 8];
            }
            #pragma unroll
            for (int an = 0; an < 4; an++) {
                int n = wn + an * 8 + g;
                bfr[an][0] = Bs[buf][kb + tig][n];
                bfr[an][1] = Bs[buf][kb + tig + 4][n];
            }
            #pragma unroll
            for (int am = 0; am < 4; am++)
                #pragma unroll
                for (int an = 0; an < 4; an++)
                    mma8(acc[am][an], afr[am], bfr[an]);
        }
    }

    #pragma unroll
    for (int am = 0; am < 4; am++) {
        int r0 = m0 + wm + am * 16 + g;
        #pragma unroll
        for (int an = 0; an < 4; an++) {
            int c0 = n0 + wn + an * 8 + 2 * tig;
            *(float2*)&C[(size_t)r0 * Dn + c0]       = make_float2(acc[am][an][0], acc[am][an][1]);
            *(float2*)&C[(size_t)(r0 + 8) * Dn + c0] = make_float2(acc[am][an][2], acc[am][an][3]);
        }
    }
}

// ---------------- sumsq of delta (from T1,T2,T3) ----------------
__global__ void k_sumsq()
{
    __shared__ float red[8];
    int i = blockIdx.x * 256 + threadIdx.x;   // BSD/4
    size_t idx = (size_t)i * 4;
    float4 t1 = *(const float4*)&g_T[idx];
    float4 t2 = *(const float4*)&g_T[Mrows * (size_t)Dn + idx];
    float4 t3 = *(const float4*)&g_T[2 * Mrows * (size_t)Dn + idx];
    float s = 0.f;
    { float re = t1.x - t2.x, im = t3.x - t1.x - t2.x; s += re * re + im * im; }
    { float re = t1.y - t2.y, im = t3.y - t1.y - t2.y; s += re * re + im * im; }
    { float re = t1.z - t2.z, im = t3.z - t1.z - t2.z; s += re * re + im * im; }
    { float re = t1.w - t2.w, im = t3.w - t1.w - t2.w; s += re * re + im * im; }
    #pragma unroll
    for (int o = 16; o > 0; o >>= 1) s += __shfl_xor_sync(0xffffffffu, s, o);
    int lane = threadIdx.x & 31, w = threadIdx.x >> 5;
    if (lane == 0) red[w] = s;
    __syncthreads();
    if (w == 0) {
        s = (lane < 8) ? red[lane] : 0.f;
        #pragma unroll
        for (int o = 4; o > 0; o >>= 1) s += __shfl_xor_sync(0xffffffffu, s, o);
        if (lane == 0) atomicAdd(&g_scal[0], s);
    }
}

// ---------------- mag = |delta| * dampf * inv_rms (tf32-rounded; overwrites g_am) --
__global__ void k_mag(int layer)
{
    int i = blockIdx.x * 256 + threadIdx.x;   // BSD/4
    float ms = g_scal[0] * (1.0f / 8388608.0f);
    ms = fmaxf(ms, 1e-12f);
    float rms = fmaxf(sqrtf(ms), 1e-3f);
    float ir = 1.0f / rms;
    int m = i >> 8, dq = i & 255;
    size_t idx = (size_t)m * Dn + dq * 4;
    float4 t1 = *(const float4*)&g_T[idx];
    float4 t2 = *(const float4*)&g_T[Mrows * (size_t)Dn + idx];
    float4 t3 = *(const float4*)&g_T[2 * Mrows * (size_t)Dn + idx];
    float4 f  = *(const float4*)&g_dampf[layer * Dn + dq * 4];
    float4 o;
    { float re = t1.x - t2.x, im = t3.x - t1.x - t2.x; o.x = f2tf_f(sqrtf(re * re + im * im) * fabsf(f.x) * ir); }
    { float re = t1.y - t2.y, im = t3.y - t1.y - t2.y; o.y = f2tf_f(sqrtf(re * re + im * im) * fabsf(f.y) * ir); }
    { float re = t1.z - t2.z, im = t3.z - t1.z - t2.z; o.z = f2tf_f(sqrtf(re * re + im * im) * fabsf(f.z) * ir); }
    { float re = t1.w - t2.w, im = t3.w - t1.w - t2.w; o.w = f2tf_f(sqrtf(re * re + im * im) * fabsf(f.w) * ir); }
    *(float4*)&g_am[idx] = o;
}

// ---------------- H = mag^T mag / S (TF32 MMA, per batch, lower-triangle tiles) ----
__global__ __launch_bounds__(256, 2) void k_H(const float* __restrict__ Hprev_in, int layer)
{
    const int batch = blockIdx.z;
    const float* __restrict__ A = g_am + (size_t)batch * Sn * Dn;  // mag [2048, 1024], pre-rounded
    float* __restrict__ H = g_H + (size_t)layer * Bn * Dn * Dn + (size_t)batch * Dn * Dn;
    const float* __restrict__ Hp = (layer == 0)
        ? (Hprev_in + (size_t)batch * Dn * Dn)
        : (g_H + (size_t)batch * Dn * Dn);

    // triangular tile decode: t -> (ti >= tj)
    const int t = blockIdx.x;
    int ti = 0;
    #pragma unroll
    for (int ii = 1; ii < 8; ii++) if (t >= ii * (ii + 1) / 2) ti = ii;
    const int tj = t - ti * (ti + 1) / 2;
    const int d0 = ti * 128;
    const int e0 = tj * 128;
    const bool offdiag = (ti != tj);

    __shared__ unsigned As[2][KT][SP];   // As[buf][s][d]
    __shared__ unsigned Bs[2][KT][SP];   // Bs[buf][s][e]

    const int tid = threadIdx.x;
    const int lane = tid & 31, wid = tid >> 5;
    const int wm = (wid >> 2) * 64;
    const int wn = (wid & 3) * 32;
    const int g = lane >> 2, tig = lane & 3;

    float acc[4][4][4];
    #pragma unroll
    for (int i = 0; i < 4; i++)
        #pragma unroll
        for (int j = 0; j < 4; j++)
            #pragma unroll
            for (int k = 0; k < 4; k++) acc[i][j][k] = 0.f;

    int buf = 0;
    for (int kt = 0; kt < Sn; kt += KT, buf ^= 1) {
        #pragma unroll
        for (int u = 0; u < 2; u++) {
            int idx = tid + u * 256;
            int sr = idx >> 5, q = idx & 31;
            float4 va = *(const float4*)&A[(size_t)(kt + sr) * Dn + d0 + q * 4];
            float4 vb = *(const float4*)&A[(size_t)(kt + sr) * Dn + e0 + q * 4];
            uint4 ua, ub;
            ua.x = __float_as_uint(va.x); ua.y = __float_as_uint(va.y);
            ua.z = __float_as_uint(va.z); ua.w = __float_as_uint(va.w);
            ub.x = __float_as_uint(vb.x); ub.y = __float_as_uint(vb.y);
            ub.z = __float_as_uint(vb.z); ub.w = __float_as_uint(vb.w);
            *(uint4*)&As[buf][sr][q * 4] = ua;
            *(uint4*)&Bs[buf][sr][q * 4] = ub;
        }
        __syncthreads();
        #pragma unroll
        for (int kb = 0; kb < KT; kb += 8) {
            unsigned afr[4][4], bfr[4][2];
            #pragma unroll
            for (int am = 0; am < 4; am++) {
                int m = wm + am * 16 + g;
                afr[am][0] = As[buf][kb + tig][m];
                afr[am][1] = As[buf][kb + tig][m + 8];
                afr[am][2] = As[buf][kb + tig + 4][m];
                afr[am][3] = As[buf][kb + tig + 4][m + 8];
            }
            #pragma unroll
            for (int an = 0; an < 4; an++) {
                int n = wn + an * 8 + g;
                bfr[an][0] = Bs[buf][kb + tig][n];
                bfr[an][1] = Bs[buf][kb + tig + 4][n];
            }
            #pragma unroll
            for (int am = 0; am < 4; am++)
                #pragma unroll
                for (int an = 0; an < 4; an++)
                    mma8(acc[am][an], afr[am], bfr[an]);
        }
    }

    const float inv_S = 1.0f / (float)Sn;
    float dsum = 0.f, psum = 0.f;
    #pragma unroll
    for (int am = 0; am < 4; am++) {
        #pragma unroll
        for (int half = 0; half < 2; half++) {
            int row = d0 + wm + am * 16 + g + half * 8;
            #pragma unroll
            for (int an = 0; an < 4; an++) {
                int col = e0 + wn + an * 8 + 2 * tig;
                size_t idx = (size_t)row * Dn + col;
                float h0 = acc[am][an][half * 2 + 0] * inv_S;
                float h1 = acc[am][an][half * 2 + 1] * inv_S;
                float2 hp = *(const float2*)&Hp[idx];
                *(float2*)&H[idx] = make_float2(h0, h1);
                float e0f = h0 - hp.x, e1f = h1 - hp.y;
                dsum += e0f * e0f + e1f * e1f;
                psum += hp.x * hp.x + hp.y * hp.y;
                if (offdiag) {
                    size_t ti0 = (size_t)col * Dn + row;
                    size_t ti1 = (size_t)(col + 1) * Dn + row;
                    float hpa = Hp[ti0], hpb = Hp[ti1];
                    H[ti0] = h0;
                    H[ti1] = h1;
                    float m0f = h0 - hpa, m1f = h1 - hpb;
                    dsum += m0f * m0f + m1f * m1f;
                    psum += hpa * hpa + hpb * hpb;
                } else {
                    if (row == col) {
                        atomicMax((int*)&g_scal[12 + batch], __float_as_int(h0));
                        atomicMin((int*)&g_scal[16 + batch], __float_as_int(h0));
                    } else if (row == col + 1) {
                        atomicMax((int*)&g_scal[12 + batch], __float_as_int(h1));
                        atomicMin((int*)&g_scal[16 + batch], __float_as_int(h1));
                    }
                }
            }
        }
    }
    #pragma unroll
    for (int o = 16; o > 0; o >>= 1) {
        dsum += __shfl_xor_sync(0xffffffffu, dsum, o);
        psum += __shfl_xor_sync(0xffffffffu, psum, o);
    }
    if (lane == 0) {
        atomicAdd(&g_scal[4 + batch], dsum);
        atomicAdd(&g_scal[8 + batch], psum);
    }
}

// ---------------- per-batch flags -> complex scale; reset scalars ----------------
__global__ void k_flags(const float* __restrict__ theta, const float* __restrict__ js,
                        const float* __restrict__ kth, int layer)
{
    int t = threadIdx.x;
    if (t < Bn) {
        float diffn = sqrtf(g_scal[4 + t]);
        float prevn = sqrtf(g_scal[8 + t]);
        float Kv = diffn / (prevn + 1e-6f);
        float dmax = g_scal[12 + t], dmin = g_scal[16 + t];
        float cond = dmax / (dmin + 1e-12f);
        float cr = (Kv > kth[layer]) ? js[layer] : 1.0f;
        float ci = 0.0f;
        if (cond > COND_TH) {
            float s, c;
            sincosf(theta[layer], &s, &c);
            ci = cr * s; cr = cr * c;
        }
        g_scal[20 + t] = cr; g_scal[24 + t] = ci;
        g_scal[4 + t] = 0.f; g_scal[8 + t] = 0.f;
        g_scal[12 + t] = 0.f; g_scal[16 + t] = __int_as_float(0x7f800000);
    }
    if (t == 8) g_scal[0] = 0.f;
}

// ---------------- residual update: psi += dampf * delta * c_b (rms cancels) -------
template <bool LAST>
__global__ void k_update(float* __restrict__ out, int layer)
{
    int i = blockIdx.x * 256 + threadIdx.x;   // BSD/4
    int m = i >> 8, dq = i & 255;
    int batch = m >> 11;
    float cr = g_scal[20 + batch], ci = g_scal[24 + batch];
    size_t tidx = (size_t)m * Dn + dq * 4;
    float4 t1 = *(const float4*)&g_T[tidx];
    float4 t2 = *(const float4*)&g_T[Mrows * (size_t)Dn + tidx];
    float4 t3 = *(const float4*)&g_T[2 * Mrows * (size_t)Dn + tidx];
    float4 f  = *(const float4*)&g_dampf[layer * Dn + dq * 4];
    float4 pr = *(const float4*)&g_psi[m * K2 + dq * 4];
    float4 pi = *(const float4*)&g_psi[m * K2 + Dn + dq * 4];

    {
        float re = t1.x - t2.x, im = t3.x - t1.x - t2.x;
        pr.x += f.x * (re * cr - im * ci);  pi.x += f.x * (re * ci + im * cr);
    }
    { float re = t1.y - t2.y, im = t3.y - t1.y - t2.y;
      pr.y += f.y * (re * cr - im * ci);  pi.y += f.y * (re * ci + im * cr); }
    { float re = t1.z - t2.z, im = t3.z - t1.z - t2.z;
      pr.z += f.z * (re * cr - im * ci);  pi.z += f.z * (re * ci + im * cr); }
    { float re = t1.w - t2.w, im = t3.w - t1.w - t2.w;
      pr.w += f.w * (re * cr - im * ci);  pi.w += f.w * (re * ci + im * cr); }

    if (LAST) {
        *(float4*)&out[m * Dn + dq * 4]       = pr;
        *(float4*)&out[BSD + m * Dn + dq * 4] = pi;
    } else {
        *(float4*)&g_psi[m * K2 + dq * 4]      = pr;
        *(float4*)&g_psi[m * K2 + Dn + dq * 4] = pi;
        float4 a3;
        a3.x = f2tf_f(pr.x + pi.x); a3.y = f2tf_f(pr.y + pi.y);
        a3.z = f2tf_f(pr.z + pi.z); a3.w = f2tf_f(pr.w + pi.w);
        *(float4*)&g_am[tidx] = a3;
    }
}

// ---------------- launch ----------------
extern "C" void kernel_launch(void* const* d_in, const int* in_sizes, int n_in,
                              void* d_out, int out_size)
{
    const float* x_real = (const float*)d_in[0];
    const float* x_imag = (const float*)d_in[1];
    const float* H_prev = (const float*)d_in[2];
    const float* W_real = (const float*)d_in[3];
    const float* W_imag = (const float*)d_in[4];
    const float* L_ops  = (const float*)d_in[5];
    const float* theta  = (const float*)d_in[6];
    const float* jscale = (const float*)d_in[7];
    const float* kth    = (const float*)d_in[8];
    float* out = (float*)d_out;

    // prep
    k_buildB3<<<(2 * Dn * Dn) / 256, 256>>>(W_real, W_imag);
    k_damp<<<8, 256>>>(L_ops);
    k_init_scal<<<1, 32>>>();
    k_pack<<<(BSD / 4) / 256, 256>>>(x_real, x_imag);

    dim3 gemm_grid(Dn / 128, Mrows / 128, 3);  // (8, 64, 3)
    dim3 H_grid(36, 1, Bn);                    // lower-triangle tiles
    const int ew_blocks = (BSD / 4) / 256;     // 8192

    for (int l = 0; l < 2; l++) {
        k_gemmT<<<gemm_grid, 256>>>(l);
        k_sumsq<<<ew_blocks, 256>>>();
        k_mag<<<ew_blocks, 256>>>(l);
        k_H<<<H_grid, 256>>>(H_prev, l);
        k_flags<<<1, 32>>>(theta, jscale, kth, l);
        if (l == 0) k_update<false><<<ew_blocks, 256>>>(out, l);
        else        k_update<true><<<ew_blocks, 256>>>(out, l);
    }
}

// round 13
// speedup vs baseline: 1.3528x; 1.3528x over previous
#include <cuda_runtime.h>
#include <math.h>

// Problem constants
#define Bn   4
#define Sn   2048
#define Dn   1024
#define Mrows (Bn*Sn)          // 8192
#define K2   (2*Dn)            // 2048
#define BSD  (Bn*Sn*Dn)        // 8388608
#define GAMMA 0.01f
#define COND_TH 100.0f

// ---------------- scratch (device globals; allocation-free) ----------------
__device__ float g_psi [Mrows * K2];          // [8192, 2048]  [Re | Im]
__device__ float g_am  [Mrows * Dn];          // dual-use: A3 = Ar+Ai, then mag (tf32-rounded)
__device__ float g_T   [3 * Mrows * Dn];      // T1, T2, T3  (each [8192,1024])
__device__ float g_B3  [2 * 3 * Dn * Dn];     // per layer: B1=Wr-I, B2=Wi, B3=B1+B2 (tf32-rounded)
__device__ float g_H   [2 * Bn * Dn * Dn];    // per-layer [B, D, D]
__device__ float g_dampf[2 * Dn];             // (1 - gamma*sum L^2)
// [0]=sumsq, [4..7]=diffsq[b], [8..11]=prevsq[b],
// [12..15]=dmax[b], [16..19]=dmin[b], [20..23]=cr[b], [24..27]=ci[b]
__device__ float g_scal[32];

__device__ __forceinline__ unsigned f2tf(float f)
{
    unsigned r;
    asm("cvt.rna.tf32.f32 %0, %1;" : "=r"(r) : "f"(f));
    return r;
}
__device__ __forceinline__ float f2tf_f(float f) { unsigned r = f2tf(f); return __uint_as_float(r); }

__device__ __forceinline__ void mma8(float* c, const unsigned* a, const unsigned* b)
{
    asm("mma.sync.aligned.m16n8k8.row.col.f32.tf32.tf32.f32 "
        "{%0,%1,%2,%3}, {%4,%5,%6,%7}, {%8,%9}, {%0,%1,%2,%3};"
        : "+f"(c[0]), "+f"(c[1]), "+f"(c[2]), "+f"(c[3])
        : "r"(a[0]), "r"(a[1]), "r"(a[2]), "r"(a[3]), "r"(b[0]), "r"(b[1]));
}

// ---------------- prep kernels ----------------
// B1 = Wr - I, B2 = Wi, B3 = B1 + B2, all [k][n] per layer, tf32-pre-rounded
__global__ void k_buildB3(const float* __restrict__ Wr, const float* __restrict__ Wi)
{
    int i = blockIdx.x * 256 + threadIdx.x;       // 2 * 1024 * 1024
    int l = i >> 20;
    int kn = i & 1048575;
    int k = kn >> 10, n = kn & 1023;
    size_t WL = (size_t)l * Dn * Dn + kn;
    float b1 = Wr[WL] - (k == n ? 1.0f : 0.0f);
    float b2 = Wi[WL];
    size_t base = (size_t)l * 3 * Dn * Dn + kn;
    g_B3[base]               = f2tf_f(b1);
    g_B3[base + Dn * Dn]     = f2tf_f(b2);
    g_B3[base + 2 * Dn * Dn] = f2tf_f(b1 + b2);
}

__global__ void k_damp(const float* __restrict__ L)
{
    int t = blockIdx.x * 256 + threadIdx.x;   // 2048
    if (t < 2 * Dn) {
        int l = t >> 10, d = t & 1023;
        float s = 0.f;
        #pragma unroll
        for (int k = 0; k < 4; k++) { float v = L[l * 4096 + k * Dn + d]; s += v * v; }
        g_dampf[t] = 1.0f - GAMMA * s;
    }
}

__global__ void k_init_scal()
{
    int t = threadIdx.x;
    if (t < 32) g_scal[t] = (t >= 16 && t < 20) ? __int_as_float(0x7f800000) : 0.0f;
}

__global__ void k_pack(const float* __restrict__ xr, const float* __restrict__ xi)
{
    int i = blockIdx.x * 256 + threadIdx.x;   // BSD/4
    int m = i >> 8, dq = i & 255;
    float4 r = *(const float4*)&xr[m * Dn + dq * 4];
    float4 im = *(const float4*)&xi[m * Dn + dq * 4];
    *(float4*)&g_psi[m * K2 + dq * 4]      = r;
    *(float4*)&g_psi[m * K2 + Dn + dq * 4] = im;
    float4 a3;
    a3.x = f2tf_f(r.x + im.x); a3.y = f2tf_f(r.y + im.y);
    a3.z = f2tf_f(r.z + im.z); a3.w = f2tf_f(r.w + im.w);
    *(float4*)&g_am[m * Dn + dq * 4] = a3;
}

// ---------------- Karatsuba T GEMMs (TF32 MMA): T_z = A_z @ B_z, K=1024 ----------
// Register prefetch + double-buffered smem: ONE __syncthreads per K-tile,
// next-tile global loads overlap the MMA block.
#define KT 16
#define SP 136    // smem row stride: 136 % 32 == 8 -> conflict-free fragment loads

__global__ __launch_bounds__(256, 2) void k_gemmT(int layer)
{
    const int z = blockIdx.z;
    const float* __restrict__ A = (z == 0) ? g_psi : (z == 1) ? (g_psi + Dn) : g_am;
    const int lda = (z == 2) ? Dn : K2;
    const bool cvtA = (z != 2);               // z=2 (A3) is pre-rounded
    const float* __restrict__ Bm = g_B3 + ((size_t)layer * 3 + z) * Dn * Dn;
    float* __restrict__ C = g_T + (size_t)z * Mrows * Dn;

    __shared__ unsigned As[2][KT][SP];   // As[buf][k][m]
    __shared__ unsigned Bs[2][KT][SP];   // Bs[buf][k][n]

    const int tid = threadIdx.x;
    const int m0 = blockIdx.y * 128;
    const int n0 = blockIdx.x * 128;
    const int lane = tid & 31, wid = tid >> 5;
    const int wm = (wid >> 2) * 64;
    const int wn = (wid & 3) * 32;
    const int g = lane >> 2, tig = lane & 3;

    float acc[4][4][4];
    #pragma unroll
    for (int i = 0; i < 4; i++)
        #pragma unroll
        for (int j = 0; j < 4; j++)
            #pragma unroll
            for (int k = 0; k < 4; k++) acc[i][j][k] = 0.f;

    float4 pa[2], pb[2];
    // prologue: prefetch tile 0
    #pragma unroll
    for (int u = 0; u < 2; u++) {
        int idx = tid + u * 256;
        pa[u] = *(const float4*)&A[(size_t)(m0 + (idx >> 2)) * lda + (idx & 3) * 4];
        pb[u] = *(const float4*)&Bm[(size_t)(idx >> 5) * Dn + n0 + (idx & 31) * 4];
    }

    int buf = 0;
    for (int kt = 0; kt < Dn; kt += KT, buf ^= 1) {
        // commit prefetched tile into buf
        #pragma unroll
        for (int u = 0; u < 2; u++) {
            int idx = tid + u * 256;
            int ar = idx >> 2, kq = idx & 3;
            if (cvtA) {
                As[buf][kq * 4 + 0][ar] = f2tf(pa[u].x);
                As[buf][kq * 4 + 1][ar] = f2tf(pa[u].y);
                As[buf][kq * 4 + 2][ar] = f2tf(pa[u].z);
                As[buf][kq * 4 + 3][ar] = f2tf(pa[u].w);
            } else {
                As[buf][kq * 4 + 0][ar] = __float_as_uint(pa[u].x);
                As[buf][kq * 4 + 1][ar] = __float_as_uint(pa[u].y);
                As[buf][kq * 4 + 2][ar] = __float_as_uint(pa[u].z);
                As[buf][kq * 4 + 3][ar] = __float_as_uint(pa[u].w);
            }
            int br = idx >> 5, bq = idx & 31;
            uint4 v;
            v.x = __float_as_uint(pb[u].x); v.y = __float_as_uint(pb[u].y);
            v.z = __float_as_uint(pb[u].z); v.w = __float_as_uint(pb[u].w);
            *(uint4*)&Bs[buf][br][bq * 4] = v;
        }
        __syncthreads();
        // prefetch next tile (overlaps the MMA block below)
        if (kt + KT < Dn) {
            #pragma unroll
            for (int u = 0; u < 2; u++) {
                int idx = tid + u * 256;
                pa[u] = *(const float4*)&A[(size_t)(m0 + (idx >> 2)) * lda + kt + KT + (idx & 3) * 4];
                pb[u] = *(const float4*)&Bm[(size_t)(kt + KT + (idx >> 5)) * Dn + n0 + (idx & 31) * 4];
            }
        }
        // compute from buf; next iteration writes buf^1 (no trailing barrier needed)
        #pragma unroll
        for (int kb = 0; kb < KT; kb += 8) {
            unsigned afr[4][4], bfr[4][2];
            #pragma unroll
            for (int am = 0; am < 4; am++) {
                int m = wm + am * 16 + g;
                afr[am][0] = As[buf][kb + tig][m];
                afr[am][1] = As[buf][kb + tig][m + 8];
                afr[am][2] = As[buf][kb + tig + 4][m];
                afr[am][3] = As[buf][kb + tig + 4][m + 8];
            }
            #pragma unroll
            for (int an = 0; an < 4; an++) {
                int n = wn + an * 8 + g;
                bfr[an][0] = Bs[buf][kb + tig][n];
                bfr[an][1] = Bs[buf][kb + tig + 4][n];
            }
            #pragma unroll
            for (int am = 0; am < 4; am++)
                #pragma unroll
                for (int an = 0; an < 4; an++)
                    mma8(acc[am][an], afr[am], bfr[an]);
        }
    }

    #pragma unroll
    for (int am = 0; am < 4; am++) {
        int r0 = m0 + wm + am * 16 + g;
        #pragma unroll
        for (int an = 0; an < 4; an++) {
            int c0 = n0 + wn + an * 8 + 2 * tig;
            *(float2*)&C[(size_t)r0 * Dn + c0]       = make_float2(acc[am][an][0], acc[am][an][1]);
            *(float2*)&C[(size_t)(r0 + 8) * Dn + c0] = make_float2(acc[am][an][2], acc[am][an][3]);
        }
    }
}

// ---------------- sumsq of delta (from T1,T2,T3) ----------------
__global__ void k_sumsq()
{
    __shared__ float red[8];
    int i = blockIdx.x * 256 + threadIdx.x;   // BSD/4
    size_t idx = (size_t)i * 4;
    float4 t1 = *(const float4*)&g_T[idx];
    float4 t2 = *(const float4*)&g_T[Mrows * (size_t)Dn + idx];
    float4 t3 = *(const float4*)&g_T[2 * Mrows * (size_t)Dn + idx];
    float s = 0.f;
    { float re = t1.x - t2.x, im = t3.x - t1.x - t2.x; s += re * re + im * im; }
    { float re = t1.y - t2.y, im = t3.y - t1.y - t2.y; s += re * re + im * im; }
    { float re = t1.z - t2.z, im = t3.z - t1.z - t2.z; s += re * re + im * im; }
    { float re = t1.w - t2.w, im = t3.w - t1.w - t2.w; s += re * re + im * im; }
    #pragma unroll
    for (int o = 16; o > 0; o >>= 1) s += __shfl_xor_sync(0xffffffffu, s, o);
    int lane = threadIdx.x & 31, w = threadIdx.x >> 5;
    if (lane == 0) red[w] = s;
    __syncthreads();
    if (w == 0) {
        s = (lane < 8) ? red[lane] : 0.f;
        #pragma unroll
        for (int o = 4; o > 0; o >>= 1) s += __shfl_xor_sync(0xffffffffu, s, o);
        if (lane == 0) atomicAdd(&g_scal[0], s);
    }
}

// ---------------- mag = |delta| * dampf * inv_rms (tf32-rounded; overwrites g_am) --
__global__ void k_mag(int layer)
{
    int i = blockIdx.x * 256 + threadIdx.x;   // BSD/4
    float ms = g_scal[0] * (1.0f / 8388608.0f);
    ms = fmaxf(ms, 1e-12f);
    float rms = fmaxf(sqrtf(ms), 1e-3f);
    float ir = 1.0f / rms;
    int m = i >> 8, dq = i & 255;
    size_t idx = (size_t)m * Dn + dq * 4;
    float4 t1 = *(const float4*)&g_T[idx];
    float4 t2 = *(const float4*)&g_T[Mrows * (size_t)Dn + idx];
    float4 t3 = *(const float4*)&g_T[2 * Mrows * (size_t)Dn + idx];
    float4 f  = *(const float4*)&g_dampf[layer * Dn + dq * 4];
    float4 o;
    { float re = t1.x - t2.x, im = t3.x - t1.x - t2.x; o.x = f2tf_f(sqrtf(re * re + im * im) * fabsf(f.x) * ir); }
    { float re = t1.y - t2.y, im = t3.y - t1.y - t2.y; o.y = f2tf_f(sqrtf(re * re + im * im) * fabsf(f.y) * ir); }
    { float re = t1.z - t2.z, im = t3.z - t1.z - t2.z; o.z = f2tf_f(sqrtf(re * re + im * im) * fabsf(f.z) * ir); }
    { float re = t1.w - t2.w, im = t3.w - t1.w - t2.w; o.w = f2tf_f(sqrtf(re * re + im * im) * fabsf(f.w) * ir); }
    *(float4*)&g_am[idx] = o;
}

// ---------------- H = mag^T mag / S (TF32 MMA, per batch, lower-triangle tiles) ----
__global__ __launch_bounds__(256, 2) void k_H(const float* __restrict__ Hprev_in, int layer)
{
    const int batch = blockIdx.z;
    const float* __restrict__ A = g_am + (size_t)batch * Sn * Dn;  // mag [2048, 1024], pre-rounded
    float* __restrict__ H = g_H + (size_t)layer * Bn * Dn * Dn + (size_t)batch * Dn * Dn;
    const float* __restrict__ Hp = (layer == 0)
        ? (Hprev_in + (size_t)batch * Dn * Dn)
        : (g_H + (size_t)batch * Dn * Dn);

    // triangular tile decode: t -> (ti >= tj)
    const int t = blockIdx.x;
    int ti = 0;
    #pragma unroll
    for (int ii = 1; ii < 8; ii++) if (t >= ii * (ii + 1) / 2) ti = ii;
    const int tj = t - ti * (ti + 1) / 2;
    const int d0 = ti * 128;
    const int e0 = tj * 128;
    const bool offdiag = (ti != tj);

    __shared__ unsigned As[2][KT][SP];   // As[buf][s][d]
    __shared__ unsigned Bs[2][KT][SP];   // Bs[buf][s][e]

    const int tid = threadIdx.x;
    const int lane = tid & 31, wid = tid >> 5;
    const int wm = (wid >> 2) * 64;
    const int wn = (wid & 3) * 32;
    const int g = lane >> 2, tig = lane & 3;

    float acc[4][4][4];
    #pragma unroll
    for (int i = 0; i < 4; i++)
        #pragma unroll
        for (int j = 0; j < 4; j++)
            #pragma unroll
            for (int k = 0; k < 4; k++) acc[i][j][k] = 0.f;

    float4 pa[2], pb[2];
    #pragma unroll
    for (int u = 0; u < 2; u++) {
        int idx = tid + u * 256;
        int sr = idx >> 5, q = idx & 31;
        pa[u] = *(const float4*)&A[(size_t)sr * Dn + d0 + q * 4];
        pb[u] = *(const float4*)&A[(size_t)sr * Dn + e0 + q * 4];
    }

    int buf = 0;
    for (int kt = 0; kt < Sn; kt += KT, buf ^= 1) {
        #pragma unroll
        for (int u = 0; u < 2; u++) {
            int idx = tid + u * 256;
            int sr = idx >> 5, q = idx & 31;
            uint4 ua, ub;
            ua.x = __float_as_uint(pa[u].x); ua.y = __float_as_uint(pa[u].y);
            ua.z = __float_as_uint(pa[u].z); ua.w = __float_as_uint(pa[u].w);
            ub.x = __float_as_uint(pb[u].x); ub.y = __float_as_uint(pb[u].y);
            ub.z = __float_as_uint(pb[u].z); ub.w = __float_as_uint(pb[u].w);
            *(uint4*)&As[buf][sr][q * 4] = ua;
            *(uint4*)&Bs[buf][sr][q * 4] = ub;
        }
        __syncthreads();
        if (kt + KT < Sn) {
            #pragma unroll
            for (int u = 0; u < 2; u++) {
                int idx = tid + u * 256;
                int sr = idx >> 5, q = idx & 31;
                pa[u] = *(const float4*)&A[(size_t)(kt + KT + sr) * Dn + d0 + q * 4];
                pb[u] = *(const float4*)&A[(size_t)(kt + KT + sr) * Dn + e0 + q * 4];
            }
        }
        #pragma unroll
        for (int kb = 0; kb < KT; kb += 8) {
            unsigned afr[4][4], bfr[4][2];
            #pragma unroll
            for (int am = 0; am < 4; am++) {
                int m = wm + am * 16 + g;
                afr[am][0] = As[buf][kb + tig][m];
                afr[am][1] = As[buf][kb + tig][m + 8];
                afr[am][2] = As[buf][kb + tig + 4][m];
                afr[am][3] = As[buf][kb + tig + 4][m + 8];
            }
            #pragma unroll
            for (int an = 0; an < 4; an++) {
                int n = wn + an * 8 + g;
                bfr[an][0] = Bs[buf][kb + tig][n];
                bfr[an][1] = Bs[buf][kb + tig + 4][n];
            }
            #pragma unroll
            for (int am = 0; am < 4; am++)
                #pragma unroll
                for (int an = 0; an < 4; an++)
                    mma8(acc[am][an], afr[am], bfr[an]);
        }
    }

    const float inv_S = 1.0f / (float)Sn;
    float dsum = 0.f, psum = 0.f;
    #pragma unroll
    for (int am = 0; am < 4; am++) {
        #pragma unroll
        for (int half = 0; half < 2; half++) {
            int row = d0 + wm + am * 16 + g + half * 8;
            #pragma unroll
            for (int an = 0; an < 4; an++) {
                int col = e0 + wn + an * 8 + 2 * tig;
                size_t idx = (size_t)row * Dn + col;
                float h0 = acc[am][an][half * 2 + 0] * inv_S;
                float h1 = acc[am][an][half * 2 + 1] * inv_S;
                float2 hp = *(const float2*)&Hp[idx];
                *(float2*)&H[idx] = make_float2(h0, h1);
                float e0f = h0 - hp.x, e1f = h1 - hp.y;
                dsum += e0f * e0f + e1f * e1f;
                psum += hp.x * hp.x + hp.y * hp.y;
                if (offdiag) {
                    size_t ti0 = (size_t)col * Dn + row;
                    size_t ti1 = (size_t)(col + 1) * Dn + row;
                    float hpa = Hp[ti0], hpb = Hp[ti1];
                    H[ti0] = h0;
                    H[ti1] = h1;
                    float m0f = h0 - hpa, m1f = h1 - hpb;
                    dsum += m0f * m0f + m1f * m1f;
                    psum += hpa * hpa + hpb * hpb;
                } else {
                    if (row == col) {
                        atomicMax((int*)&g_scal[12 + batch], __float_as_int(h0));
                        atomicMin((int*)&g_scal[16 + batch], __float_as_int(h0));
                    } else if (row == col + 1) {
                        atomicMax((int*)&g_scal[12 + batch], __float_as_int(h1));
                        atomicMin((int*)&g_scal[16 + batch], __float_as_int(h1));
                    }
                }
            }
        }
    }
    #pragma unroll
    for (int o = 16; o > 0; o >>= 1) {
        dsum += __shfl_xor_sync(0xffffffffu, dsum, o);
        psum += __shfl_xor_sync(0xffffffffu, psum, o);
    }
    if (lane == 0) {
        atomicAdd(&g_scal[4 + batch], dsum);
        atomicAdd(&g_scal[8 + batch], psum);
    }
}

// ---------------- per-batch flags -> complex scale; reset scalars ----------------
__global__ void k_flags(const float* __restrict__ theta, const float* __restrict__ js,
                        const float* __restrict__ kth, int layer)
{
    int t = threadIdx.x;
    if (t < Bn) {
        float diffn = sqrtf(g_scal[4 + t]);
        float prevn = sqrtf(g_scal[8 + t]);
        float Kv = diffn / (prevn + 1e-6f);
        float dmax = g_scal[12 + t], dmin = g_scal[16 + t];
        float cond = dmax / (dmin + 1e-12f);
        float cr = (Kv > kth[layer]) ? js[layer] : 1.0f;
        float ci = 0.0f;
        if (cond > COND_TH) {
            float s, c;
            sincosf(theta[layer], &s, &c);
            ci = cr * s; cr = cr * c;
        }
        g_scal[20 + t] = cr; g_scal[24 + t] = ci;
        g_scal[4 + t] = 0.f; g_scal[8 + t] = 0.f;
        g_scal[12 + t] = 0.f; g_scal[16 + t] = __int_as_float(0x7f800000);
    }
    if (t == 8) g_scal[0] = 0.f;
}

// ---------------- residual update: psi += dampf * delta * c_b (rms cancels) -------
template <bool LAST>
__global__ void k_update(float* __restrict__ out, int layer)
{
    int i = blockIdx.x * 256 + threadIdx.x;   // BSD/4
    int m = i >> 8, dq = i & 255;
    int batch = m >> 11;
    float cr = g_scal[20 + batch], ci = g_scal[24 + batch];
    size_t tidx = (size_t)m * Dn + dq * 4;
    float4 t1 = *(const float4*)&g_T[tidx];
    float4 t2 = *(const float4*)&g_T[Mrows * (size_t)Dn + tidx];
    float4 t3 = *(const float4*)&g_T[2 * Mrows * (size_t)Dn + tidx];
    float4 f  = *(const float4*)&g_dampf[layer * Dn + dq * 4];
    float4 pr = *(const float4*)&g_psi[m * K2 + dq * 4];
    float4 pi = *(const float4*)&g_psi[m * K2 + Dn + dq * 4];

    {
        float re = t1.x - t2.x, im = t3.x - t1.x - t2.x;
        pr.x += f.x * (re * cr - im * ci);  pi.x += f.x * (re * ci + im * cr);
    }
    { float re = t1.y - t2.y, im = t3.y - t1.y - t2.y;
      pr.y += f.y * (re * cr - im * ci);  pi.y += f.y * (re * ci + im * cr); }
    { float re = t1.z - t2.z, im = t3.z - t1.z - t2.z;
      pr.z += f.z * (re * cr - im * ci);  pi.z += f.z * (re * ci + im * cr); }
    { float re = t1.w - t2.w, im = t3.w - t1.w - t2.w;
      pr.w += f.w * (re * cr - im * ci);  pi.w += f.w * (re * ci + im * cr); }

    if (LAST) {
        *(float4*)&out[m * Dn + dq * 4]       = pr;
        *(float4*)&out[BSD + m * Dn + dq * 4] = pi;
    } else {
        *(float4*)&g_psi[m * K2 + dq * 4]      = pr;
        *(float4*)&g_psi[m * K2 + Dn + dq * 4] = pi;
        float4 a3;
        a3.x = f2tf_f(pr.x + pi.x); a3.y = f2tf_f(pr.y + pi.y);
        a3.z = f2tf_f(pr.z + pi.z); a3.w = f2tf_f(pr.w + pi.w);
        *(float4*)&g_am[tidx] = a3;
    }
}

// ---------------- launch ----------------
extern "C" void kernel_launch(void* const* d_in, const int* in_sizes, int n_in,
                              void* d_out, int out_size)
{
    const float* x_real = (const float*)d_in[0];
    const float* x_imag = (const float*)d_in[1];
    const float* H_prev = (const float*)d_in[2];
    const float* W_real = (const float*)d_in[3];
    const float* W_imag = (const float*)d_in[4];
    const float* L_ops  = (const float*)d_in[5];
    const float* theta  = (const float*)d_in[6];
    const float* jscale = (const float*)d_in[7];
    const float* kth    = (const float*)d_in[8];
    float* out = (float*)d_out;

    // prep
    k_buildB3<<<(2 * Dn * Dn) / 256, 256>>>(W_real, W_imag);
    k_damp<<<8, 256>>>(L_ops);
    k_init_scal<<<1, 32>>>();
    k_pack<<<(BSD / 4) / 256, 256>>>(x_real, x_imag);

    dim3 gemm_grid(Dn / 128, Mrows / 128, 3);  // (8, 64, 3)
    dim3 H_grid(36, 1, Bn);                    // lower-triangle tiles
    const int ew_blocks = (BSD / 4) / 256;     // 8192

    for (int l = 0; l < 2; l++) {
        k_gemmT<<<gemm_grid, 256>>>(l);
        k_sumsq<<<ew_blocks, 256>>>();
        k_mag<<<ew_blocks, 256>>>(l);
        k_H<<<H_grid, 256>>>(H_prev, l);
        k_flags<<<1, 32>>>(theta, jscale, kth, l);
        if (l == 0) k_update<false><<<ew_blocks, 256>>>(out, l);
        else        k_update<true><<<ew_blocks, 256>>>(out, l);
    }
}

// round 14
// speedup vs baseline: 1.4003x; 1.0351x over previous
#include <cuda_runtime.h>
#include <math.h>

// Problem constants
#define Bn   4
#define Sn   2048
#define Dn   1024
#define Mrows (Bn*Sn)          // 8192
#define K2   (2*Dn)            // 2048
#define BSD  (Bn*Sn*Dn)        // 8388608
#define GAMMA 0.01f
#define COND_TH 100.0f

// ---------------- scratch (device globals; allocation-free) ----------------
__device__ float g_psi [Mrows * K2];          // [8192, 2048]  [Re | Im]  (state after layer 0)
__device__ float g_am  [Mrows * Dn];          // dual-use: A3 = Ar+Ai, then mag' (both tf32-rounded)
__device__ float g_T   [3 * Mrows * Dn];      // T1, T2, T3  (each [8192,1024])
__device__ float g_B3  [2 * 3 * Dn * Dn];     // per layer: B1=Wr-I, B2=Wi, B3=B1+B2 (tf32-rounded)
__device__ float g_H   [2 * Bn * Dn * Dn];    // per-layer [B, D, D]
__device__ float g_dampf[2 * Dn];             // (1 - gamma*sum L^2)
// [0]=sumsq, [4..7]=diffsq[b], [8..11]=prevsq[b],
// [12..15]=dmax[b], [16..19]=dmin[b], [20..23]=cr[b], [24..27]=ci[b]
__device__ float g_scal[32];

__device__ __forceinline__ unsigned f2tf(float f)
{
    unsigned r;
    asm("cvt.rna.tf32.f32 %0, %1;" : "=r"(r) : "f"(f));
    return r;
}
__device__ __forceinline__ float f2tf_f(float f) { unsigned r = f2tf(f); return __uint_as_float(r); }

__device__ __forceinline__ void mma8(float* c, const unsigned* a, const unsigned* b)
{
    asm("mma.sync.aligned.m16n8k8.row.col.f32.tf32.tf32.f32 "
        "{%0,%1,%2,%3}, {%4,%5,%6,%7}, {%8,%9}, {%0,%1,%2,%3};"
        : "+f"(c[0]), "+f"(c[1]), "+f"(c[2]), "+f"(c[3])
        : "r"(a[0]), "r"(a[1]), "r"(a[2]), "r"(a[3]), "r"(b[0]), "r"(b[1]));
}

// ---------------- prep kernels ----------------
// B1 = Wr - I, B2 = Wi, B3 = B1 + B2, all [k][n] per layer, tf32-pre-rounded
__global__ void k_buildB3(const float* __restrict__ Wr, const float* __restrict__ Wi)
{
    int i = blockIdx.x * 256 + threadIdx.x;       // 2 * 1024 * 1024
    int l = i >> 20;
    int kn = i & 1048575;
    int k = kn >> 10, n = kn & 1023;
    size_t WL = (size_t)l * Dn * Dn + kn;
    float b1 = Wr[WL] - (k == n ? 1.0f : 0.0f);
    float b2 = Wi[WL];
    size_t base = (size_t)l * 3 * Dn * Dn + kn;
    g_B3[base]               = f2tf_f(b1);
    g_B3[base + Dn * Dn]     = f2tf_f(b2);
    g_B3[base + 2 * Dn * Dn] = f2tf_f(b1 + b2);
}

__global__ void k_damp(const float* __restrict__ L)
{
    int t = blockIdx.x * 256 + threadIdx.x;   // 2048
    if (t < 2 * Dn) {
        int l = t >> 10, d = t & 1023;
        float s = 0.f;
        #pragma unroll
        for (int k = 0; k < 4; k++) { float v = L[l * 4096 + k * Dn + d]; s += v * v; }
        g_dampf[t] = 1.0f - GAMMA * s;
    }
}

__global__ void k_init_scal()
{
    int t = threadIdx.x;
    if (t < 32) g_scal[t] = (t >= 16 && t < 20) ? __int_as_float(0x7f800000) : 0.0f;
}

// A3 = tf32(xr + xi) only; psi state is materialized by the layer-0 update.
__global__ void k_a3(const float* __restrict__ xr, const float* __restrict__ xi)
{
    int i = blockIdx.x * 256 + threadIdx.x;   // BSD/4
    size_t idx = (size_t)i * 4;
    float4 r = *(const float4*)&xr[idx];
    float4 im = *(const float4*)&xi[idx];
    float4 a3;
    a3.x = f2tf_f(r.x + im.x); a3.y = f2tf_f(r.y + im.y);
    a3.z = f2tf_f(r.z + im.z); a3.w = f2tf_f(r.w + im.w);
    *(float4*)&g_am[idx] = a3;
}

// ---------------- Karatsuba T GEMMs (TF32 MMA): T_z = A_z @ B_z, K=1024 ----------
// Register prefetch + double-buffered smem: ONE __syncthreads per K-tile.
#define KT 16
#define SP 136    // smem row stride: 136 % 32 == 8 -> conflict-free fragment loads

__global__ __launch_bounds__(256, 2) void k_gemmT(const float* __restrict__ xr,
                                                  const float* __restrict__ xi,
                                                  int layer)
{
    const int z = blockIdx.z;
    const float* __restrict__ A;
    int lda;
    if (z == 2)            { A = g_am; lda = Dn; }
    else if (layer == 0)   { A = (z == 0) ? xr : xi; lda = Dn; }
    else                   { A = (z == 0) ? g_psi : (g_psi + Dn); lda = K2; }
    const bool cvtA = (z != 2);               // z=2 (A3) is pre-rounded
    const float* __restrict__ Bm = g_B3 + ((size_t)layer * 3 + z) * Dn * Dn;
    float* __restrict__ C = g_T + (size_t)z * Mrows * Dn;

    __shared__ unsigned As[2][KT][SP];   // As[buf][k][m]
    __shared__ unsigned Bs[2][KT][SP];   // Bs[buf][k][n]

    const int tid = threadIdx.x;
    const int m0 = blockIdx.y * 128;
    const int n0 = blockIdx.x * 128;
    const int lane = tid & 31, wid = tid >> 5;
    const int wm = (wid >> 2) * 64;
    const int wn = (wid & 3) * 32;
    const int g = lane >> 2, tig = lane & 3;

    float acc[4][4][4];
    #pragma unroll
    for (int i = 0; i < 4; i++)
        #pragma unroll
        for (int j = 0; j < 4; j++)
            #pragma unroll
            for (int k = 0; k < 4; k++) acc[i][j][k] = 0.f;

    float4 pa[2], pb[2];
    #pragma unroll
    for (int u = 0; u < 2; u++) {
        int idx = tid + u * 256;
        pa[u] = *(const float4*)&A[(size_t)(m0 + (idx >> 2)) * lda + (idx & 3) * 4];
        pb[u] = *(const float4*)&Bm[(size_t)(idx >> 5) * Dn + n0 + (idx & 31) * 4];
    }

    int buf = 0;
    for (int kt = 0; kt < Dn; kt += KT, buf ^= 1) {
        #pragma unroll
        for (int u = 0; u < 2; u++) {
            int idx = tid + u * 256;
            int ar = idx >> 2, kq = idx & 3;
            if (cvtA) {
                As[buf][kq * 4 + 0][ar] = f2tf(pa[u].x);
                As[buf][kq * 4 + 1][ar] = f2tf(pa[u].y);
                As[buf][kq * 4 + 2][ar] = f2tf(pa[u].z);
                As[buf][kq * 4 + 3][ar] = f2tf(pa[u].w);
            } else {
                As[buf][kq * 4 + 0][ar] = __float_as_uint(pa[u].x);
                As[buf][kq * 4 + 1][ar] = __float_as_uint(pa[u].y);
                As[buf][kq * 4 + 2][ar] = __float_as_uint(pa[u].z);
                As[buf][kq * 4 + 3][ar] = __float_as_uint(pa[u].w);
            }
            int br = idx >> 5, bq = idx & 31;
            uint4 v;
            v.x = __float_as_uint(pb[u].x); v.y = __float_as_uint(pb[u].y);
            v.z = __float_as_uint(pb[u].z); v.w = __float_as_uint(pb[u].w);
            *(uint4*)&Bs[buf][br][bq * 4] = v;
        }
        __syncthreads();
        if (kt + KT < Dn) {
            #pragma unroll
            for (int u = 0; u < 2; u++) {
                int idx = tid + u * 256;
                pa[u] = *(const float4*)&A[(size_t)(m0 + (idx >> 2)) * lda + kt + KT + (idx & 3) * 4];
                pb[u] = *(const float4*)&Bm[(size_t)(kt + KT + (idx >> 5)) * Dn + n0 + (idx & 31) * 4];
            }
        }
        #pragma unroll
        for (int kb = 0; kb < KT; kb += 8) {
            unsigned afr[4][4], bfr[4][2];
            #pragma unroll
            for (int am = 0; am < 4; am++) {
                int m = wm + am * 16 + g;
                afr[am][0] = As[buf][kb + tig][m];
                afr[am][1] = As[buf][kb + tig][m + 8];
                afr[am][2] = As[buf][kb + tig + 4][m];
                afr[am][3] = As[buf][kb + tig + 4][m + 8];
            }
            #pragma unroll
            for (int an = 0; an < 4; an++) {
                int n = wn + an * 8 + g;
                bfr[an][0] = Bs[buf][kb + tig][n];
                bfr[an][1] = Bs[buf][kb + tig + 4][n];
            }
            #pragma unroll
            for (int am = 0; am < 4; am++)
                #pragma unroll
                for (int an = 0; an < 4; an++)
                    mma8(acc[am][an], afr[am], bfr[an]);
        }
    }

    #pragma unroll
    for (int am = 0; am < 4; am++) {
        int r0 = m0 + wm + am * 16 + g;
        #pragma unroll
        for (int an = 0; an < 4; an++) {
            int c0 = n0 + wn + an * 8 + 2 * tig;
            *(float2*)&C[(size_t)r0 * Dn + c0]       = make_float2(acc[am][an][0], acc[am][an][1]);
            *(float2*)&C[(size_t)(r0 + 8) * Dn + c0] = make_float2(acc[am][an][2], acc[am][an][3]);
        }
    }
}

// ---------------- fused: mag' = tf32(|delta|*|dampf|) (unscaled) + sumsq(delta) ----
__global__ void k_magsum(int layer)
{
    __shared__ float red[8];
    int i = blockIdx.x * 256 + threadIdx.x;   // BSD/4
    int m = i >> 8, dq = i & 255;
    size_t idx = (size_t)m * Dn + dq * 4;
    float4 t1 = *(const float4*)&g_T[idx];
    float4 t2 = *(const float4*)&g_T[Mrows * (size_t)Dn + idx];
    float4 t3 = *(const float4*)&g_T[2 * Mrows * (size_t)Dn + idx];
    float4 f  = *(const float4*)&g_dampf[layer * Dn + dq * 4];
    float s = 0.f;
    float4 o;
    { float re = t1.x - t2.x, im = t3.x - t1.x - t2.x; float q = re * re + im * im; s += q;
      o.x = f2tf_f(sqrtf(q) * fabsf(f.x)); }
    { float re = t1.y - t2.y, im = t3.y - t1.y - t2.y; float q = re * re + im * im; s += q;
      o.y = f2tf_f(sqrtf(q) * fabsf(f.y)); }
    { float re = t1.z - t2.z, im = t3.z - t1.z - t2.z; float q = re * re + im * im; s += q;
      o.z = f2tf_f(sqrtf(q) * fabsf(f.z)); }
    { float re = t1.w - t2.w, im = t3.w - t1.w - t2.w; float q = re * re + im * im; s += q;
      o.w = f2tf_f(sqrtf(q) * fabsf(f.w)); }
    *(float4*)&g_am[idx] = o;
    #pragma unroll
    for (int o2 = 16; o2 > 0; o2 >>= 1) s += __shfl_xor_sync(0xffffffffu, s, o2);
    int lane = threadIdx.x & 31, w = threadIdx.x >> 5;
    if (lane == 0) red[w] = s;
    __syncthreads();
    if (w == 0) {
        s = (lane < 8) ? red[lane] : 0.f;
        #pragma unroll
        for (int o2 = 4; o2 > 0; o2 >>= 1) s += __shfl_xor_sync(0xffffffffu, s, o2);
        if (lane == 0) atomicAdd(&g_scal[0], s);
    }
}

// ---------------- H = mag'^T mag' /(S*rms^2) (TF32 MMA, lower-triangle tiles) ------
__global__ __launch_bounds__(256, 2) void k_H(const float* __restrict__ Hprev_in, int layer)
{
    const int batch = blockIdx.z;
    const float* __restrict__ A = g_am + (size_t)batch * Sn * Dn;  // mag' [2048, 1024], pre-rounded
    float* __restrict__ H = g_H + (size_t)layer * Bn * Dn * Dn + (size_t)batch * Dn * Dn;
    const float* __restrict__ Hp = (layer == 0)
        ? (Hprev_in + (size_t)batch * Dn * Dn)
        : (g_H + (size_t)batch * Dn * Dn);

    // triangular tile decode: t -> (ti >= tj)
    const int t = blockIdx.x;
    int ti = 0;
    #pragma unroll
    for (int ii = 1; ii < 8; ii++) if (t >= ii * (ii + 1) / 2) ti = ii;
    const int tj = t - ti * (ti + 1) / 2;
    const int d0 = ti * 128;
    const int e0 = tj * 128;
    const bool offdiag = (ti != tj);

    __shared__ unsigned As[2][KT][SP];   // As[buf][s][d]
    __shared__ unsigned Bs[2][KT][SP];   // Bs[buf][s][e]

    const int tid = threadIdx.x;
    const int lane = tid & 31, wid = tid >> 5;
    const int wm = (wid >> 2) * 64;
    const int wn = (wid & 3) * 32;
    const int g = lane >> 2, tig = lane & 3;

    float acc[4][4][4];
    #pragma unroll
    for (int i = 0; i < 4; i++)
        #pragma unroll
        for (int j = 0; j < 4; j++)
            #pragma unroll
            for (int k = 0; k < 4; k++) acc[i][j][k] = 0.f;

    float4 pa[2], pb[2];
    #pragma unroll
    for (int u = 0; u < 2; u++) {
        int idx = tid + u * 256;
        int sr = idx >> 5, q = idx & 31;
        pa[u] = *(const float4*)&A[(size_t)sr * Dn + d0 + q * 4];
        pb[u] = *(const float4*)&A[(size_t)sr * Dn + e0 + q * 4];
    }

    int buf = 0;
    for (int kt = 0; kt < Sn; kt += KT, buf ^= 1) {
        #pragma unroll
        for (int u = 0; u < 2; u++) {
            int idx = tid + u * 256;
            int sr = idx >> 5, q = idx & 31;
            uint4 ua, ub;
            ua.x = __float_as_uint(pa[u].x); ua.y = __float_as_uint(pa[u].y);
            ua.z = __float_as_uint(pa[u].z); ua.w = __float_as_uint(pa[u].w);
            ub.x = __float_as_uint(pb[u].x); ub.y = __float_as_uint(pb[u].y);
            ub.z = __float_as_uint(pb[u].z); ub.w = __float_as_uint(pb[u].w);
            *(uint4*)&As[buf][sr][q * 4] = ua;
            *(uint4*)&Bs[buf][sr][q * 4] = ub;
        }
        __syncthreads();
        if (kt + KT < Sn) {
            #pragma unroll
            for (int u = 0; u < 2; u++) {
                int idx = tid + u * 256;
                int sr = idx >> 5, q = idx & 31;
                pa[u] = *(const float4*)&A[(size_t)(kt + KT + sr) * Dn + d0 + q * 4];
                pb[u] = *(const float4*)&A[(size_t)(kt + KT + sr) * Dn + e0 + q * 4];
            }
        }
        #pragma unroll
        for (int kb = 0; kb < KT; kb += 8) {
            unsigned afr[4][4], bfr[4][2];
            #pragma unroll
            for (int am = 0; am < 4; am++) {
                int m = wm + am * 16 + g;
                afr[am][0] = As[buf][kb + tig][m];
                afr[am][1] = As[buf][kb + tig][m + 8];
                afr[am][2] = As[buf][kb + tig + 4][m];
                afr[am][3] = As[buf][kb + tig + 4][m + 8];
            }
            #pragma unroll
            for (int an = 0; an < 4; an++) {
                int n = wn + an * 8 + g;
                bfr[an][0] = Bs[buf][kb + tig][n];
                bfr[an][1] = Bs[buf][kb + tig + 4][n];
            }
            #pragma unroll
            for (int am = 0; am < 4; am++)
                #pragma unroll
                for (int an = 0; an < 4; an++)
                    mma8(acc[am][an], afr[am], bfr[an]);
        }
    }

    // scale = 1/(S*rms^2): rms from fused sumsq (completed before this kernel)
    float ms = fmaxf(g_scal[0] * (1.0f / 8388608.0f), 1e-12f);
    float rms = fmaxf(sqrtf(ms), 1e-3f);
    const float sc = (1.0f / (float)Sn) / (rms * rms);

    float dsum = 0.f, psum = 0.f;
    #pragma unroll
    for (int am = 0; am < 4; am++) {
        #pragma unroll
        for (int half = 0; half < 2; half++) {
            int row = d0 + wm + am * 16 + g + half * 8;
            #pragma unroll
            for (int an = 0; an < 4; an++) {
                int col = e0 + wn + an * 8 + 2 * tig;
                size_t idx = (size_t)row * Dn + col;
                float h0 = acc[am][an][half * 2 + 0] * sc;
                float h1 = acc[am][an][half * 2 + 1] * sc;
                float2 hp = *(const float2*)&Hp[idx];
                *(float2*)&H[idx] = make_float2(h0, h1);
                float e0f = h0 - hp.x, e1f = h1 - hp.y;
                dsum += e0f * e0f + e1f * e1f;
                psum += hp.x * hp.x + hp.y * hp.y;
                if (offdiag) {
                    size_t ti0 = (size_t)col * Dn + row;
                    size_t ti1 = (size_t)(col + 1) * Dn + row;
                    float hpa = Hp[ti0], hpb = Hp[ti1];
                    H[ti0] = h0;
                    H[ti1] = h1;
                    float m0f = h0 - hpa, m1f = h1 - hpb;
                    dsum += m0f * m0f + m1f * m1f;
                    psum += hpa * hpa + hpb * hpb;
                } else {
                    if (row == col) {
                        atomicMax((int*)&g_scal[12 + batch], __float_as_int(h0));
                        atomicMin((int*)&g_scal[16 + batch], __float_as_int(h0));
                    } else if (row == col + 1) {
                        atomicMax((int*)&g_scal[12 + batch], __float_as_int(h1));
                        atomicMin((int*)&g_scal[16 + batch], __float_as_int(h1));
                    }
                }
            }
        }
    }
    #pragma unroll
    for (int o = 16; o > 0; o >>= 1) {
        dsum += __shfl_xor_sync(0xffffffffu, dsum, o);
        psum += __shfl_xor_sync(0xffffffffu, psum, o);
    }
    if (lane == 0) {
        atomicAdd(&g_scal[4 + batch], dsum);
        atomicAdd(&g_scal[8 + batch], psum);
    }
}

// ---------------- per-batch flags -> complex scale; reset scalars ----------------
__global__ void k_flags(const float* __restrict__ theta, const float* __restrict__ js,
                        const float* __restrict__ kth, int layer)
{
    int t = threadIdx.x;
    if (t < Bn) {
        float diffn = sqrtf(g_scal[4 + t]);
        float prevn = sqrtf(g_scal[8 + t]);
        float Kv = diffn / (prevn + 1e-6f);
        float dmax = g_scal[12 + t], dmin = g_scal[16 + t];
        float cond = dmax / (dmin + 1e-12f);
        float cr = (Kv > kth[layer]) ? js[layer] : 1.0f;
        float ci = 0.0f;
        if (cond > COND_TH) {
            float s, c;
            sincosf(theta[layer], &s, &c);
            ci = cr * s; cr = cr * c;
        }
        g_scal[20 + t] = cr; g_scal[24 + t] = ci;
        g_scal[4 + t] = 0.f; g_scal[8 + t] = 0.f;
        g_scal[12 + t] = 0.f; g_scal[16 + t] = __int_as_float(0x7f800000);
    }
    if (t == 8) g_scal[0] = 0.f;
}

// ---------------- residual update: psi += dampf * delta * c_b (rms cancels) -------
template <int LAYER>
__global__ void k_update(float* __restrict__ out,
                         const float* __restrict__ xr, const float* __restrict__ xi)
{
    int i = blockIdx.x * 256 + threadIdx.x;   // BSD/4
    int m = i >> 8, dq = i & 255;
    int batch = m >> 11;
    float cr = g_scal[20 + batch], ci = g_scal[24 + batch];
    size_t tidx = (size_t)m * Dn + dq * 4;
    float4 t1 = *(const float4*)&g_T[tidx];
    float4 t2 = *(const float4*)&g_T[Mrows * (size_t)Dn + tidx];
    float4 t3 = *(const float4*)&g_T[2 * Mrows * (size_t)Dn + tidx];
    float4 f  = *(const float4*)&g_dampf[LAYER * Dn + dq * 4];
    float4 pr, pi;
    if (LAYER == 0) {
        pr = *(const float4*)&xr[tidx];
        pi = *(const float4*)&xi[tidx];
    } else {
        pr = *(const float4*)&g_psi[m * K2 + dq * 4];
        pi = *(const float4*)&g_psi[m * K2 + Dn + dq * 4];
    }

    {
        float re = t1.x - t2.x, im = t3.x - t1.x - t2.x;
        pr.x += f.x * (re * cr - im * ci);  pi.x += f.x * (re * ci + im * cr);
    }
    { float re = t1.y - t2.y, im = t3.y - t1.y - t2.y;
      pr.y += f.y * (re * cr - im * ci);  pi.y += f.y * (re * ci + im * cr); }
    { float re = t1.z - t2.z, im = t3.z - t1.z - t2.z;
      pr.z += f.z * (re * cr - im * ci);  pi.z += f.z * (re * ci + im * cr); }
    { float re = t1.w - t2.w, im = t3.w - t1.w - t2.w;
      pr.w += f.w * (re * cr - im * ci);  pi.w += f.w * (re * ci + im * cr); }

    if (LAYER == 1) {
        *(float4*)&out[tidx]       = pr;
        *(float4*)&out[BSD + tidx] = pi;
    } else {
        *(float4*)&g_psi[m * K2 + dq * 4]      = pr;
        *(float4*)&g_psi[m * K2 + Dn + dq * 4] = pi;
        float4 a3;
        a3.x = f2tf_f(pr.x + pi.x); a3.y = f2tf_f(pr.y + pi.y);
        a3.z = f2tf_f(pr.z + pi.z); a3.w = f2tf_f(pr.w + pi.w);
        *(float4*)&g_am[tidx] = a3;
    }
}

// ---------------- launch ----------------
extern "C" void kernel_launch(void* const* d_in, const int* in_sizes, int n_in,
                              void* d_out, int out_size)
{
    const float* x_real = (const float*)d_in[0];
    const float* x_imag = (const float*)d_in[1];
    const float* H_prev = (const float*)d_in[2];
    const float* W_real = (const float*)d_in[3];
    const float* W_imag = (const float*)d_in[4];
    const float* L_ops  = (const float*)d_in[5];
    const float* theta  = (const float*)d_in[6];
    const float* jscale = (const float*)d_in[7];
    const float* kth    = (const float*)d_in[8];
    float* out = (float*)d_out;

    // prep
    k_buildB3<<<(2 * Dn * Dn) / 256, 256>>>(W_real, W_imag);
    k_damp<<<8, 256>>>(L_ops);
    k_init_scal<<<1, 32>>>();
    k_a3<<<(BSD / 4) / 256, 256>>>(x_real, x_imag);

    dim3 gemm_grid(Dn / 128, Mrows / 128, 3);  // (8, 64, 3)
    dim3 H_grid(36, 1, Bn);                    // lower-triangle tiles
    const int ew_blocks = (BSD / 4) / 256;     // 8192

    // layer 0 (psi state comes straight from x_real/x_imag)
    k_gemmT<<<gemm_grid, 256>>>(x_real, x_imag, 0);
    k_magsum<<<ew_blocks, 256>>>(0);
    k_H<<<H_grid, 256>>>(H_prev, 0);
    k_flags<<<1, 32>>>(theta, jscale, kth, 0);
    k_update<0><<<ew_blocks, 256>>>(out, x_real, x_imag);

    // layer 1 (psi state in g_psi)
    k_gemmT<<<gemm_grid, 256>>>(x_real, x_imag, 1);
    k_magsum<<<ew_blocks, 256>>>(1);
    k_H<<<H_grid, 256>>>(H_prev, 1);
    k_flags<<<1, 32>>>(theta, jscale, kth, 1);
    k_update<1><<<ew_blocks, 256>>>(out, x_real, x_imag);
}

// round 15
// speedup vs baseline: 1.6466x; 1.1759x over previous
#include <cuda_runtime.h>
#include <math.h>
#include <stdint.h>

// Problem constants
#define Bn   4
#define Sn   2048
#define Dn   1024
#define Mrows 8192
#define K2   2048
#define BSD  8388608
#define GAMMA 0.01f
#define COND_TH 100.0f

// GEMM tiling
#define KT   16
#define ASP  28                 // A smem row: 16 data + 12 pad floats (112B, 16B-aligned)
#define BSP  136                // B smem row stride (8 mod 32 -> conflict-free)
#define A_STG (128*ASP)         // 3584 floats per A stage
#define B_STG (KT*BSP)          // 2176 floats per B stage
#define GEMM_DYN (3*(A_STG+B_STG)*4)   // 69120 B
#define H_DYN    (3*2*B_STG*4)         // 52224 B

// ---------------- scratch (device globals; allocation-free) ----------------
__device__ float g_psi[2 * BSD];   // unrounded psi after layer 0: [0..BSD) re, [BSD..) im
__device__ float g_xt0[BSD];       // tf32(x_re), then tf32(psi_re)
__device__ float g_xt1[BSD];       // tf32(x_im), then tf32(psi_im)
__device__ float g_am [BSD];       // tf32(a3), then mag' (unscaled)
__device__ float g_T  [3 * BSD];   // T1, T2, T3
__device__ float g_B3 [2 * 3 * Dn * Dn];  // per layer: B1=Wr-I, B2=Wi, B3 (tf32-rounded)
__device__ float g_H  [Bn * Dn * Dn];     // layer-0 H only
__device__ float g_dampf[2 * Dn];
// [0]=sumsq, [4..7]=diffsq[b], [8..11]=prevsq[b],
// [12..15]=dmax[b], [16..19]=dmin[b], [20..23]=cr[b], [24..27]=ci[b]
__device__ float g_scal[32];

__device__ __forceinline__ unsigned f2tf(float f)
{
    unsigned r;
    asm("cvt.rna.tf32.f32 %0, %1;" : "=r"(r) : "f"(f));
    return r;
}
__device__ __forceinline__ float f2tf_f(float f) { unsigned r = f2tf(f); return __uint_as_float(r); }

__device__ __forceinline__ void mma8(float* c, const unsigned* a, const unsigned* b)
{
    asm("mma.sync.aligned.m16n8k8.row.col.f32.tf32.tf32.f32 "
        "{%0,%1,%2,%3}, {%4,%5,%6,%7}, {%8,%9}, {%0,%1,%2,%3};"
        : "+f"(c[0]), "+f"(c[1]), "+f"(c[2]), "+f"(c[3])
        : "r"(a[0]), "r"(a[1]), "r"(a[2]), "r"(a[3]), "r"(b[0]), "r"(b[1]));
}

__device__ __forceinline__ uint32_t smem_u32(const void* p)
{
    uint32_t a;
    asm("{ .reg .u64 t; cvta.to.shared.u64 t, %1; cvt.u32.u64 %0, t; }" : "=r"(a) : "l"(p));
    return a;
}
__device__ __forceinline__ void cpa16(uint32_t dst, const void* src)
{
    asm volatile("cp.async.cg.shared.global [%0], [%1], 16;" :: "r"(dst), "l"(src));
}
#define CP_COMMIT() asm volatile("cp.async.commit_group;")
#define CP_WAIT1()  asm volatile("cp.async.wait_group 1;")

// ---------------- prep kernels ----------------
__global__ void k_buildB3(const float* __restrict__ Wr, const float* __restrict__ Wi)
{
    int i = blockIdx.x * 256 + threadIdx.x;       // 2 * 1024 * 1024
    int l = i >> 20;
    int kn = i & 1048575;
    int k = kn >> 10, n = kn & 1023;
    size_t WL = (size_t)l * Dn * Dn + kn;
    float b1 = Wr[WL] - (k == n ? 1.0f : 0.0f);
    float b2 = Wi[WL];
    size_t base = (size_t)l * 3 * Dn * Dn + kn;
    g_B3[base]               = f2tf_f(b1);
    g_B3[base + Dn * Dn]     = f2tf_f(b2);
    g_B3[base + 2 * Dn * Dn] = f2tf_f(b1 + b2);
}

__global__ void k_damp(const float* __restrict__ L)
{
    int t = blockIdx.x * 256 + threadIdx.x;   // 2048
    if (t < 2 * Dn) {
        int l = t >> 10, d = t & 1023;
        float s = 0.f;
        #pragma unroll
        for (int k = 0; k < 4; k++) { float v = L[l * 4096 + k * Dn + d]; s += v * v; }
        g_dampf[t] = 1.0f - GAMMA * s;
    }
}

__global__ void k_init_scal()
{
    int t = threadIdx.x;
    if (t < 32) g_scal[t] = (t >= 16 && t < 20) ? __int_as_float(0x7f800000) : 0.0f;
}

// xt0 = tf32(xr), xt1 = tf32(xi), a3 = tf32(xr+xi)
__global__ void k_prep(const float* __restrict__ xr, const float* __restrict__ xi)
{
    int i = blockIdx.x * 256 + threadIdx.x;   // BSD/4
    size_t idx = (size_t)i * 4;
    float4 r = *(const float4*)&xr[idx];
    float4 im = *(const float4*)&xi[idx];
    float4 a, b, c;
    a.x = f2tf_f(r.x);  a.y = f2tf_f(r.y);  a.z = f2tf_f(r.z);  a.w = f2tf_f(r.w);
    b.x = f2tf_f(im.x); b.y = f2tf_f(im.y); b.z = f2tf_f(im.z); b.w = f2tf_f(im.w);
    c.x = f2tf_f(r.x + im.x); c.y = f2tf_f(r.y + im.y);
    c.z = f2tf_f(r.z + im.z); c.w = f2tf_f(r.w + im.w);
    *(float4*)&g_xt0[idx] = a;
    *(float4*)&g_xt1[idx] = b;
    *(float4*)&g_am[idx]  = c;
}

// ---------------- Karatsuba T GEMMs: cp.async 3-stage pipeline ----------------
__device__ __forceinline__ void gemm_issue(const float* __restrict__ A,
                                           const float* __restrict__ Bm,
                                           uint32_t aB, uint32_t bB,
                                           int s, int kt, int m0, int n0, int tid)
{
    #pragma unroll
    for (int u = 0; u < 2; u++) {
        int c = tid + u * 256;
        int row = c >> 2, q = c & 3;
        cpa16(aB + (unsigned)(s * A_STG + row * ASP) * 4 + q * 16,
              A + (size_t)(m0 + row) * Dn + kt + q * 4);
    }
    #pragma unroll
    for (int u = 0; u < 2; u++) {
        int c = tid + u * 256;
        int row = c >> 5, q = c & 31;
        cpa16(bB + (unsigned)(s * B_STG + row * BSP) * 4 + q * 16,
              Bm + (size_t)(kt + row) * Dn + n0 + q * 4);
    }
    CP_COMMIT();
}

__global__ __launch_bounds__(256, 2) void k_gemmT(int layer)
{
    extern __shared__ unsigned dsm[];
    const int z = blockIdx.z;
    const float* __restrict__ A = (z == 0) ? g_xt0 : (z == 1) ? g_xt1 : g_am;
    const float* __restrict__ Bm = g_B3 + ((size_t)layer * 3 + z) * Dn * Dn;
    float* __restrict__ C = g_T + (size_t)z * BSD;

    const int tid = threadIdx.x;
    const int m0 = blockIdx.y * 128;
    const int n0 = blockIdx.x * 128;
    const int lane = tid & 31, wid = tid >> 5;
    const int wm = (wid >> 2) * 64;
    const int wn = (wid & 3) * 32;
    const int g = lane >> 2, tig = lane & 3;

    uint32_t sbase = smem_u32(dsm);
    uint32_t aB = sbase, bB = sbase + (unsigned)(3 * A_STG) * 4;
    const unsigned* Bsm = dsm + 3 * A_STG;

    float acc[4][4][4];
    #pragma unroll
    for (int i = 0; i < 4; i++)
        #pragma unroll
        for (int j = 0; j < 4; j++)
            #pragma unroll
            for (int k = 0; k < 4; k++) acc[i][j][k] = 0.f;

    gemm_issue(A, Bm, aB, bB, 0, 0, m0, n0, tid);
    gemm_issue(A, Bm, aB, bB, 1, KT, m0, n0, tid);

    int cur = 0, nxt = 2;
    const int NT = Dn / KT;   // 64
    for (int t = 0; t < NT; t++) {
        CP_WAIT1();
        __syncthreads();
        if (t + 2 < NT) gemm_issue(A, Bm, aB, bB, nxt, (t + 2) * KT, m0, n0, tid);
        else CP_COMMIT();

        const unsigned* Ast = dsm + cur * A_STG;
        const unsigned* Bst = Bsm + cur * B_STG;
        #pragma unroll
        for (int kb = 0; kb < KT; kb += 8) {
            unsigned afr[4][4], bfr[4][2];
            #pragma unroll
            for (int am = 0; am < 4; am++) {
                int mrow = (wm + am * 16 + g) * ASP;
                afr[am][0] = Ast[mrow + kb + tig];
                afr[am][1] = Ast[mrow + 8 * ASP + kb + tig];
                afr[am][2] = Ast[mrow + kb + tig + 4];
                afr[am][3] = Ast[mrow + 8 * ASP + kb + tig + 4];
            }
            #pragma unroll
            for (int an = 0; an < 4; an++) {
                int n = wn + an * 8 + g;
                bfr[an][0] = Bst[(kb + tig) * BSP + n];
                bfr[an][1] = Bst[(kb + tig + 4) * BSP + n];
            }
            #pragma unroll
            for (int am = 0; am < 4; am++)
                #pragma unroll
                for (int an = 0; an < 4; an++)
                    mma8(acc[am][an], afr[am], bfr[an]);
        }
        cur = (cur == 2) ? 0 : cur + 1;
        nxt = (nxt == 2) ? 0 : nxt + 1;
    }

    #pragma unroll
    for (int am = 0; am < 4; am++) {
        int r0 = m0 + wm + am * 16 + g;
        #pragma unroll
        for (int an = 0; an < 4; an++) {
            int c0 = n0 + wn + an * 8 + 2 * tig;
            *(float2*)&C[(size_t)r0 * Dn + c0]       = make_float2(acc[am][an][0], acc[am][an][1]);
            *(float2*)&C[(size_t)(r0 + 8) * Dn + c0] = make_float2(acc[am][an][2], acc[am][an][3]);
        }
    }
}

// ---------------- fused: mag' = tf32(|delta|*|dampf|) (unscaled) + sumsq(delta) ----
__global__ void k_magsum(int layer)
{
    __shared__ float red[8];
    int i = blockIdx.x * 256 + threadIdx.x;   // BSD/4
    int m = i >> 8, dq = i & 255;
    size_t idx = (size_t)m * Dn + dq * 4;
    float4 t1 = *(const float4*)&g_T[idx];
    float4 t2 = *(const float4*)&g_T[BSD + idx];
    float4 t3 = *(const float4*)&g_T[2 * (size_t)BSD + idx];
    float4 f  = *(const float4*)&g_dampf[layer * Dn + dq * 4];
    float s = 0.f;
    float4 o;
    { float re = t1.x - t2.x, im = t3.x - t1.x - t2.x; float q = re * re + im * im; s += q;
      o.x = f2tf_f(sqrtf(q) * fabsf(f.x)); }
    { float re = t1.y - t2.y, im = t3.y - t1.y - t2.y; float q = re * re + im * im; s += q;
      o.y = f2tf_f(sqrtf(q) * fabsf(f.y)); }
    { float re = t1.z - t2.z, im = t3.z - t1.z - t2.z; float q = re * re + im * im; s += q;
      o.z = f2tf_f(sqrtf(q) * fabsf(f.z)); }
    { float re = t1.w - t2.w, im = t3.w - t1.w - t2.w; float q = re * re + im * im; s += q;
      o.w = f2tf_f(sqrtf(q) * fabsf(f.w)); }
    *(float4*)&g_am[idx] = o;
    #pragma unroll
    for (int o2 = 16; o2 > 0; o2 >>= 1) s += __shfl_xor_sync(0xffffffffu, s, o2);
    int lane = threadIdx.x & 31, w = threadIdx.x >> 5;
    if (lane == 0) red[w] = s;
    __syncthreads();
    if (w == 0) {
        s = (lane < 8) ? red[lane] : 0.f;
        #pragma unroll
        for (int o2 = 4; o2 > 0; o2 >>= 1) s += __shfl_xor_sync(0xffffffffu, s, o2);
        if (lane == 0) atomicAdd(&g_scal[0], s);
    }
}

// ---------------- H = mag'^T mag' /(S*rms^2): cp.async 3-stage, triangular --------
__device__ __forceinline__ void h_issue(const float* __restrict__ A,
                                        uint32_t aB, uint32_t bB,
                                        int s, int kt, int d0, int e0, int tid)
{
    #pragma unroll
    for (int u = 0; u < 2; u++) {
        int c = tid + u * 256;
        int row = c >> 5, q = c & 31;
        cpa16(aB + (unsigned)(s * B_STG + row * BSP) * 4 + q * 16,
              A + (size_t)(kt + row) * Dn + d0 + q * 4);
        cpa16(bB + (unsigned)(s * B_STG + row * BSP) * 4 + q * 16,
              A + (size_t)(kt + row) * Dn + e0 + q * 4);
    }
    CP_COMMIT();
}

template <int LAYER>
__global__ __launch_bounds__(256, 2) void k_H(const float* __restrict__ Hprev_in)
{
    extern __shared__ unsigned dsm[];
    const int batch = blockIdx.z;
    const float* __restrict__ A = g_am + (size_t)batch * Sn * Dn;
    float* __restrict__ H = g_H + (size_t)batch * Dn * Dn;
    const float* __restrict__ Hp = (LAYER == 0)
        ? (Hprev_in + (size_t)batch * Dn * Dn)
        : (g_H + (size_t)batch * Dn * Dn);

    const int t = blockIdx.x;
    int ti = 0;
    #pragma unroll
    for (int ii = 1; ii < 8; ii++) if (t >= ii * (ii + 1) / 2) ti = ii;
    const int tj = t - ti * (ti + 1) / 2;
    const int d0 = ti * 128;
    const int e0 = tj * 128;
    const bool offdiag = (ti != tj);

    const int tid = threadIdx.x;
    const int lane = tid & 31, wid = tid >> 5;
    const int wm = (wid >> 2) * 64;
    const int wn = (wid & 3) * 32;
    const int g = lane >> 2, tig = lane & 3;

    uint32_t sbase = smem_u32(dsm);
    uint32_t aB = sbase, bB = sbase + (unsigned)(3 * B_STG) * 4;
    const unsigned* Bsm = dsm + 3 * B_STG;

    float acc[4][4][4];
    #pragma unroll
    for (int i = 0; i < 4; i++)
        #pragma unroll
        for (int j = 0; j < 4; j++)
            #pragma unroll
            for (int k = 0; k < 4; k++) acc[i][j][k] = 0.f;

    h_issue(A, aB, bB, 0, 0, d0, e0, tid);
    h_issue(A, aB, bB, 1, KT, d0, e0, tid);

    int cur = 0, nxt = 2;
    const int NT = Sn / KT;   // 128
    for (int tt = 0; tt < NT; tt++) {
        CP_WAIT1();
        __syncthreads();
        if (tt + 2 < NT) h_issue(A, aB, bB, nxt, (tt + 2) * KT, d0, e0, tid);
        else CP_COMMIT();

        const unsigned* Ast = dsm + cur * B_STG;
        const unsigned* Bst = Bsm + cur * B_STG;
        #pragma unroll
        for (int kb = 0; kb < KT; kb += 8) {
            unsigned afr[4][4], bfr[4][2];
            #pragma unroll
            for (int am = 0; am < 4; am++) {
                int m = wm + am * 16 + g;
                afr[am][0] = Ast[(kb + tig) * BSP + m];
                afr[am][1] = Ast[(kb + tig) * BSP + m + 8];
                afr[am][2] = Ast[(kb + tig + 4) * BSP + m];
                afr[am][3] = Ast[(kb + tig + 4) * BSP + m + 8];
            }
            #pragma unroll
            for (int an = 0; an < 4; an++) {
                int n = wn + an * 8 + g;
                bfr[an][0] = Bst[(kb + tig) * BSP + n];
                bfr[an][1] = Bst[(kb + tig + 4) * BSP + n];
            }
            #pragma unroll
            for (int am = 0; am < 4; am++)
                #pragma unroll
                for (int an = 0; an < 4; an++)
                    mma8(acc[am][an], afr[am], bfr[an]);
        }
        cur = (cur == 2) ? 0 : cur + 1;
        nxt = (nxt == 2) ? 0 : nxt + 1;
    }

    // scale = 1/(S*rms^2): rms from fused sumsq (completed before this kernel)
    float ms = fmaxf(g_scal[0] * (1.0f / 8388608.0f), 1e-12f);
    float rms = fmaxf(sqrtf(ms), 1e-3f);
    const float sc = (1.0f / (float)Sn) / (rms * rms);

    float dsum = 0.f, psum = 0.f;
    #pragma unroll
    for (int am = 0; am < 4; am++) {
        #pragma unroll
        for (int half = 0; half < 2; half++) {
            int row = d0 + wm + am * 16 + g + half * 8;
            #pragma unroll
            for (int an = 0; an < 4; an++) {
                int col = e0 + wn + an * 8 + 2 * tig;
                size_t idx = (size_t)row * Dn + col;
                float h0 = acc[am][an][half * 2 + 0] * sc;
                float h1 = acc[am][an][half * 2 + 1] * sc;
                float2 hp = *(const float2*)&Hp[idx];
                if (LAYER == 0) *(float2*)&H[idx] = make_float2(h0, h1);
                float e0f = h0 - hp.x, e1f = h1 - hp.y;
                dsum += e0f * e0f + e1f * e1f;
                psum += hp.x * hp.x + hp.y * hp.y;
                if (offdiag) {
                    size_t ti0 = (size_t)col * Dn + row;
                    size_t ti1 = (size_t)(col + 1) * Dn + row;
                    float hpa = Hp[ti0], hpb = Hp[ti1];
                    if (LAYER == 0) { H[ti0] = h0; H[ti1] = h1; }
                    float m0f = h0 - hpa, m1f = h1 - hpb;
                    dsum += m0f * m0f + m1f * m1f;
                    psum += hpa * hpa + hpb * hpb;
                } else {
                    if (row == col) {
                        atomicMax((int*)&g_scal[12 + batch], __float_as_int(h0));
                        atomicMin((int*)&g_scal[16 + batch], __float_as_int(h0));
                    } else if (row == col + 1) {
                        atomicMax((int*)&g_scal[12 + batch], __float_as_int(h1));
                        atomicMin((int*)&g_scal[16 + batch], __float_as_int(h1));
                    }
                }
            }
        }
    }
    #pragma unroll
    for (int o = 16; o > 0; o >>= 1) {
        dsum += __shfl_xor_sync(0xffffffffu, dsum, o);
        psum += __shfl_xor_sync(0xffffffffu, psum, o);
    }
    if (lane == 0) {
        atomicAdd(&g_scal[4 + batch], dsum);
        atomicAdd(&g_scal[8 + batch], psum);
    }
}

// ---------------- per-batch flags -> complex scale; reset scalars ----------------
__global__ void k_flags(const float* __restrict__ theta, const float* __restrict__ js,
                        const float* __restrict__ kth, int layer)
{
    int t = threadIdx.x;
    if (t < Bn) {
        float diffn = sqrtf(g_scal[4 + t]);
        float prevn = sqrtf(g_scal[8 + t]);
        float Kv = diffn / (prevn + 1e-6f);
        float dmax = g_scal[12 + t], dmin = g_scal[16 + t];
        float cond = dmax / (dmin + 1e-12f);
        float cr = (Kv > kth[layer]) ? js[layer] : 1.0f;
        float ci = 0.0f;
        if (cond > COND_TH) {
            float s, c;
            sincosf(theta[layer], &s, &c);
            ci = cr * s; cr = cr * c;
        }
        g_scal[20 + t] = cr; g_scal[24 + t] = ci;
        g_scal[4 + t] = 0.f; g_scal[8 + t] = 0.f;
        g_scal[12 + t] = 0.f; g_scal[16 + t] = __int_as_float(0x7f800000);
    }
    if (t == 8) g_scal[0] = 0.f;
}

// ---------------- residual update: psi += dampf * delta * c_b (rms cancels) -------
template <int LAYER>
__global__ void k_update(float* __restrict__ out,
                         const float* __restrict__ xr, const float* __restrict__ xi)
{
    int i = blockIdx.x * 256 + threadIdx.x;   // BSD/4
    int m = i >> 8, dq = i & 255;
    int batch = m >> 11;
    float cr = g_scal[20 + batch], ci = g_scal[24 + batch];
    size_t tidx = (size_t)m * Dn + dq * 4;
    float4 t1 = *(const float4*)&g_T[tidx];
    float4 t2 = *(const float4*)&g_T[BSD + tidx];
    float4 t3 = *(const float4*)&g_T[2 * (size_t)BSD + tidx];
    float4 f  = *(const float4*)&g_dampf[LAYER * Dn + dq * 4];
    float4 pr, pi;
    if (LAYER == 0) {
        pr = *(const float4*)&xr[tidx];
        pi = *(const float4*)&xi[tidx];
    } else {
        pr = *(const float4*)&g_psi[tidx];
        pi = *(const float4*)&g_psi[BSD + tidx];
    }

    {
        float re = t1.x - t2.x, im = t3.x - t1.x - t2.x;
        pr.x += f.x * (re * cr - im * ci);  pi.x += f.x * (re * ci + im * cr);
    }
    { float re = t1.y - t2.y, im = t3.y - t1.y - t2.y;
      pr.y += f.y * (re * cr - im * ci);  pi.y += f.y * (re * ci + im * cr); }
    { float re = t1.z - t2.z, im = t3.z - t1.z - t2.z;
      pr.z += f.z * (re * cr - im * ci);  pi.z += f.z * (re * ci + im * cr); }
    { float re = t1.w - t2.w, im = t3.w - t1.w - t2.w;
      pr.w += f.w * (re * cr - im * ci);  pi.w += f.w * (re * ci + im * cr); }

    if (LAYER == 1) {
        *(float4*)&out[tidx]       = pr;
        *(float4*)&out[BSD + tidx] = pi;
    } else {
        *(float4*)&g_psi[tidx]       = pr;
        *(float4*)&g_psi[BSD + tidx] = pi;
        float4 a, b, c;
        a.x = f2tf_f(pr.x); a.y = f2tf_f(pr.y); a.z = f2tf_f(pr.z); a.w = f2tf_f(pr.w);
        b.x = f2tf_f(pi.x); b.y = f2tf_f(pi.y); b.z = f2tf_f(pi.z); b.w = f2tf_f(pi.w);
        c.x = f2tf_f(pr.x + pi.x); c.y = f2tf_f(pr.y + pi.y);
        c.z = f2tf_f(pr.z + pi.z); c.w = f2tf_f(pr.w + pi.w);
        *(float4*)&g_xt0[tidx] = a;
        *(float4*)&g_xt1[tidx] = b;
        *(float4*)&g_am[tidx]  = c;
    }
}

// ---------------- launch ----------------
extern "C" void kernel_launch(void* const* d_in, const int* in_sizes, int n_in,
                              void* d_out, int out_size)
{
    const float* x_real = (const float*)d_in[0];
    const float* x_imag = (const float*)d_in[1];
    const float* H_prev = (const float*)d_in[2];
    const float* W_real = (const float*)d_in[3];
    const float* W_imag = (const float*)d_in[4];
    const float* L_ops  = (const float*)d_in[5];
    const float* theta  = (const float*)d_in[6];
    const float* jscale = (const float*)d_in[7];
    const float* kth    = (const float*)d_in[8];
    float* out = (float*)d_out;

    cudaFuncSetAttribute(k_gemmT, cudaFuncAttributeMaxDynamicSharedMemorySize, GEMM_DYN);
    cudaFuncSetAttribute(k_H<0>,  cudaFuncAttributeMaxDynamicSharedMemorySize, H_DYN);
    cudaFuncSetAttribute(k_H<1>,  cudaFuncAttributeMaxDynamicSharedMemorySize, H_DYN);

    // prep
    k_buildB3<<<(2 * Dn * Dn) / 256, 256>>>(W_real, W_imag);
    k_damp<<<8, 256>>>(L_ops);
    k_init_scal<<<1, 32>>>();
    k_prep<<<(BSD / 4) / 256, 256>>>(x_real, x_imag);

    dim3 gemm_grid(Dn / 128, Mrows / 128, 3);  // (8, 64, 3)
    dim3 H_grid(36, 1, Bn);                    // lower-triangle tiles
    const int ew_blocks = (BSD / 4) / 256;     // 8192

    // layer 0
    k_gemmT<<<gemm_grid, 256, GEMM_DYN>>>(0);
    k_magsum<<<ew_blocks, 256>>>(0);
    k_H<0><<<H_grid, 256, H_DYN>>>(H_prev);
    k_flags<<<1, 32>>>(theta, jscale, kth, 0);
    k_update<0><<<ew_blocks, 256>>>(out, x_real, x_imag);

    // layer 1
    k_gemmT<<<gemm_grid, 256, GEMM_DYN>>>(1);
    k_magsum<<<ew_blocks, 256>>>(1);
    k_H<1><<<H_grid, 256, H_DYN>>>(H_prev);
    k_flags<<<1, 32>>>(theta, jscale, kth, 1);
    k_update<1><<<ew_blocks, 256>>>(out, x_real, x_imag);
}

// round 16
// speedup vs baseline: 1.7481x; 1.0617x over previous
#include <cuda_runtime.h>
#include <math.h>
#include <stdint.h>

// Problem constants
#define Bn   4
#define Sn   2048
#define Dn   1024
#define Mrows 8192
#define K2   2048
#define BSD  8388608
#define GAMMA 0.01f
#define COND_TH 100.0f

// T-GEMM tiling (KT=32)
#define KT   32
#define ASP  36                 // A smem row: 32 data + 4 pad floats (144B, 16B-aligned)
#define BSP  136                // B smem row stride (8 mod 32 -> conflict-free)
#define A_STG (128*ASP)         // 4608 floats per A stage
#define B_STG (KT*BSP)          // 4352 floats per B stage
#define GEMM_DYN (3*(A_STG+B_STG)*4)   // 107520 B

// H tiling (KT=16)
#define HKT  16
#define HB_STG (HKT*BSP)        // 2176 floats per stage
#define H_DYN (3*2*HB_STG*4)    // 52224 B

// ---------------- scratch (device globals; allocation-free) ----------------
__device__ float g_psi[2 * BSD];   // unrounded psi after layer 0: [0..BSD) re, [BSD..) im
__device__ float g_xt0[BSD];       // tf32(x_re), then tf32(psi_re)
__device__ float g_xt1[BSD];       // tf32(x_im), then tf32(psi_im)
__device__ float g_am [BSD];       // tf32(a3), then mag' (unscaled)
__device__ float g_T  [3 * BSD];   // T1, T2, T3
__device__ float g_B3 [2 * 3 * Dn * Dn];  // per layer: B1=Wr-I, B2=Wi, B3 (tf32-rounded)
__device__ float g_H  [Bn * Dn * Dn];     // layer-0 H only
__device__ float g_dampf[2 * Dn];
// [0]=sumsq, [4..7]=diffsq[b], [8..11]=prevsq[b],
// [12..15]=dmax[b], [16..19]=dmin[b], [20..23]=cr[b], [24..27]=ci[b]
__device__ float g_scal[32];
__device__ int   g_ctr;            // last-CTA counter for fused flags

__device__ __forceinline__ unsigned f2tf(float f)
{
    unsigned r;
    asm("cvt.rna.tf32.f32 %0, %1;" : "=r"(r) : "f"(f));
    return r;
}
__device__ __forceinline__ float f2tf_f(float f) { unsigned r = f2tf(f); return __uint_as_float(r); }

__device__ __forceinline__ void mma8(float* c, const unsigned* a, const unsigned* b)
{
    asm("mma.sync.aligned.m16n8k8.row.col.f32.tf32.tf32.f32 "
        "{%0,%1,%2,%3}, {%4,%5,%6,%7}, {%8,%9}, {%0,%1,%2,%3};"
        : "+f"(c[0]), "+f"(c[1]), "+f"(c[2]), "+f"(c[3])
        : "r"(a[0]), "r"(a[1]), "r"(a[2]), "r"(a[3]), "r"(b[0]), "r"(b[1]));
}

__device__ __forceinline__ uint32_t smem_u32(const void* p)
{
    uint32_t a;
    asm("{ .reg .u64 t; cvta.to.shared.u64 t, %1; cvt.u32.u64 %0, t; }" : "=r"(a) : "l"(p));
    return a;
}
__device__ __forceinline__ void cpa16(uint32_t dst, const void* src)
{
    asm volatile("cp.async.cg.shared.global [%0], [%1], 16;" :: "r"(dst), "l"(src));
}
#define CP_COMMIT() asm volatile("cp.async.commit_group;")
#define CP_WAIT1()  asm volatile("cp.async.wait_group 1;")

// ---------------- prep kernels ----------------
__global__ void k_buildB3(const float* __restrict__ Wr, const float* __restrict__ Wi)
{
    int i = blockIdx.x * 256 + threadIdx.x;       // 2 * 1024 * 1024
    int l = i >> 20;
    int kn = i & 1048575;
    int k = kn >> 10, n = kn & 1023;
    size_t WL = (size_t)l * Dn * Dn + kn;
    float b1 = Wr[WL] - (k == n ? 1.0f : 0.0f);
    float b2 = Wi[WL];
    size_t base = (size_t)l * 3 * Dn * Dn + kn;
    g_B3[base]               = f2tf_f(b1);
    g_B3[base + Dn * Dn]     = f2tf_f(b2);
    g_B3[base + 2 * Dn * Dn] = f2tf_f(b1 + b2);
}

__global__ void k_damp(const float* __restrict__ L)
{
    int t = blockIdx.x * 256 + threadIdx.x;   // 2048
    if (t < 2 * Dn) {
        int l = t >> 10, d = t & 1023;
        float s = 0.f;
        #pragma unroll
        for (int k = 0; k < 4; k++) { float v = L[l * 4096 + k * Dn + d]; s += v * v; }
        g_dampf[t] = 1.0f - GAMMA * s;
    }
}

__global__ void k_init_scal()
{
    int t = threadIdx.x;
    if (t < 32) g_scal[t] = (t >= 16 && t < 20) ? __int_as_float(0x7f800000) : 0.0f;
    if (t == 0) g_ctr = 0;
}

// xt0 = tf32(xr), xt1 = tf32(xi), a3 = tf32(xr+xi)
__global__ void k_prep(const float* __restrict__ xr, const float* __restrict__ xi)
{
    int i = blockIdx.x * 256 + threadIdx.x;   // BSD/4
    size_t idx = (size_t)i * 4;
    float4 r = *(const float4*)&xr[idx];
    float4 im = *(const float4*)&xi[idx];
    float4 a, b, c;
    a.x = f2tf_f(r.x);  a.y = f2tf_f(r.y);  a.z = f2tf_f(r.z);  a.w = f2tf_f(r.w);
    b.x = f2tf_f(im.x); b.y = f2tf_f(im.y); b.z = f2tf_f(im.z); b.w = f2tf_f(im.w);
    c.x = f2tf_f(r.x + im.x); c.y = f2tf_f(r.y + im.y);
    c.z = f2tf_f(r.z + im.z); c.w = f2tf_f(r.w + im.w);
    *(float4*)&g_xt0[idx] = a;
    *(float4*)&g_xt1[idx] = b;
    *(float4*)&g_am[idx]  = c;
}

// ---------------- Karatsuba T GEMMs: cp.async 3-stage pipeline, KT=32 -------------
__device__ __forceinline__ void gemm_issue(const float* __restrict__ A,
                                           const float* __restrict__ Bm,
                                           uint32_t aB, uint32_t bB,
                                           int s, int kt, int m0, int n0, int tid)
{
    #pragma unroll
    for (int u = 0; u < 4; u++) {
        int c = tid + u * 256;
        int row = c >> 3, q = c & 7;
        cpa16(aB + (unsigned)(s * A_STG + row * ASP + q * 4) * 4,
              A + (size_t)(m0 + row) * Dn + kt + q * 4);
    }
    #pragma unroll
    for (int u = 0; u < 4; u++) {
        int c = tid + u * 256;
        int row = c >> 5, q = c & 31;
        cpa16(bB + (unsigned)(s * B_STG + row * BSP + q * 4) * 4,
              Bm + (size_t)(kt + row) * Dn + n0 + q * 4);
    }
    CP_COMMIT();
}

__global__ __launch_bounds__(256, 2) void k_gemmT(int layer)
{
    extern __shared__ unsigned dsm[];
    const int z = blockIdx.z;
    const float* __restrict__ A = (z == 0) ? g_xt0 : (z == 1) ? g_xt1 : g_am;
    const float* __restrict__ Bm = g_B3 + ((size_t)layer * 3 + z) * Dn * Dn;
    float* __restrict__ C = g_T + (size_t)z * BSD;

    const int tid = threadIdx.x;
    const int m0 = blockIdx.y * 128;
    const int n0 = blockIdx.x * 128;
    const int lane = tid & 31, wid = tid >> 5;
    const int wm = (wid >> 2) * 64;
    const int wn = (wid & 3) * 32;
    const int g = lane >> 2, tig = lane & 3;

    uint32_t sbase = smem_u32(dsm);
    uint32_t aB = sbase, bB = sbase + (unsigned)(3 * A_STG) * 4;
    const unsigned* Bsm = dsm + 3 * A_STG;

    float acc[4][4][4];
    #pragma unroll
    for (int i = 0; i < 4; i++)
        #pragma unroll
        for (int j = 0; j < 4; j++)
            #pragma unroll
            for (int k = 0; k < 4; k++) acc[i][j][k] = 0.f;

    gemm_issue(A, Bm, aB, bB, 0, 0, m0, n0, tid);
    gemm_issue(A, Bm, aB, bB, 1, KT, m0, n0, tid);

    int cur = 0, nxt = 2;
    const int NT = Dn / KT;   // 32
    for (int t = 0; t < NT; t++) {
        CP_WAIT1();
        __syncthreads();
        if (t + 2 < NT) gemm_issue(A, Bm, aB, bB, nxt, (t + 2) * KT, m0, n0, tid);
        else CP_COMMIT();

        const unsigned* Ast = dsm + cur * A_STG;
        const unsigned* Bst = Bsm + cur * B_STG;
        #pragma unroll
        for (int kb = 0; kb < KT; kb += 8) {
            unsigned afr[4][4], bfr[4][2];
            #pragma unroll
            for (int am = 0; am < 4; am++) {
                int mrow = (wm + am * 16 + g) * ASP;
                afr[am][0] = Ast[mrow + kb + tig];
                afr[am][1] = Ast[mrow + 8 * ASP + kb + tig];
                afr[am][2] = Ast[mrow + kb + tig + 4];
                afr[am][3] = Ast[mrow + 8 * ASP + kb + tig + 4];
            }
            #pragma unroll
            for (int an = 0; an < 4; an++) {
                int n = wn + an * 8 + g;
                bfr[an][0] = Bst[(kb + tig) * BSP + n];
                bfr[an][1] = Bst[(kb + tig + 4) * BSP + n];
            }
            #pragma unroll
            for (int am = 0; am < 4; am++)
                #pragma unroll
                for (int an = 0; an < 4; an++)
                    mma8(acc[am][an], afr[am], bfr[an]);
        }
        cur = (cur == 2) ? 0 : cur + 1;
        nxt = (nxt == 2) ? 0 : nxt + 1;
    }

    #pragma unroll
    for (int am = 0; am < 4; am++) {
        int r0 = m0 + wm + am * 16 + g;
        #pragma unroll
        for (int an = 0; an < 4; an++) {
            int c0 = n0 + wn + an * 8 + 2 * tig;
            *(float2*)&C[(size_t)r0 * Dn + c0]       = make_float2(acc[am][an][0], acc[am][an][1]);
            *(float2*)&C[(size_t)(r0 + 8) * Dn + c0] = make_float2(acc[am][an][2], acc[am][an][3]);
        }
    }
}

// ---------------- fused: mag' = tf32(|delta|*|dampf|) (unscaled) + sumsq(delta) ----
__global__ void k_magsum(int layer)
{
    __shared__ float red[8];
    int i = blockIdx.x * 256 + threadIdx.x;   // BSD/4
    int m = i >> 8, dq = i & 255;
    size_t idx = (size_t)m * Dn + dq * 4;
    float4 t1 = *(const float4*)&g_T[idx];
    float4 t2 = *(const float4*)&g_T[BSD + idx];
    float4 t3 = *(const float4*)&g_T[2 * (size_t)BSD + idx];
    float4 f  = *(const float4*)&g_dampf[layer * Dn + dq * 4];
    float s = 0.f;
    float4 o;
    { float re = t1.x - t2.x, im = t3.x - t1.x - t2.x; float q = re * re + im * im; s += q;
      o.x = f2tf_f(sqrtf(q) * fabsf(f.x)); }
    { float re = t1.y - t2.y, im = t3.y - t1.y - t2.y; float q = re * re + im * im; s += q;
      o.y = f2tf_f(sqrtf(q) * fabsf(f.y)); }
    { float re = t1.z - t2.z, im = t3.z - t1.z - t2.z; float q = re * re + im * im; s += q;
      o.z = f2tf_f(sqrtf(q) * fabsf(f.z)); }
    { float re = t1.w - t2.w, im = t3.w - t1.w - t2.w; float q = re * re + im * im; s += q;
      o.w = f2tf_f(sqrtf(q) * fabsf(f.w)); }
    *(float4*)&g_am[idx] = o;
    #pragma unroll
    for (int o2 = 16; o2 > 0; o2 >>= 1) s += __shfl_xor_sync(0xffffffffu, s, o2);
    int lane = threadIdx.x & 31, w = threadIdx.x >> 5;
    if (lane == 0) red[w] = s;
    __syncthreads();
    if (w == 0) {
        s = (lane < 8) ? red[lane] : 0.f;
        #pragma unroll
        for (int o2 = 4; o2 > 0; o2 >>= 1) s += __shfl_xor_sync(0xffffffffu, s, o2);
        if (lane == 0) atomicAdd(&g_scal[0], s);
    }
}

// ---------------- H = mag'^T mag' /(S*rms^2): cp.async 3-stage, triangular,
//                  with fused per-batch flags in the last CTA --------------------
__device__ __forceinline__ void h_issue(const float* __restrict__ A,
                                        uint32_t aB, uint32_t bB,
                                        int s, int kt, int d0, int e0, int tid)
{
    #pragma unroll
    for (int u = 0; u < 2; u++) {
        int c = tid + u * 256;
        int row = c >> 5, q = c & 31;
        cpa16(aB + (unsigned)(s * HB_STG + row * BSP + q * 4) * 4,
              A + (size_t)(kt + row) * Dn + d0 + q * 4);
        cpa16(bB + (unsigned)(s * HB_STG + row * BSP + q * 4) * 4,
              A + (size_t)(kt + row) * Dn + e0 + q * 4);
    }
    CP_COMMIT();
}

template <int LAYER>
__global__ __launch_bounds__(256, 2) void k_H(const float* __restrict__ Hprev_in,
                                              const float* __restrict__ theta,
                                              const float* __restrict__ js,
                                              const float* __restrict__ kth)
{
    extern __shared__ unsigned dsm[];
    const int batch = blockIdx.z;
    const float* __restrict__ A = g_am + (size_t)batch * Sn * Dn;
    float* __restrict__ H = g_H + (size_t)batch * Dn * Dn;
    const float* __restrict__ Hp = (LAYER == 0)
        ? (Hprev_in + (size_t)batch * Dn * Dn)
        : (g_H + (size_t)batch * Dn * Dn);

    const int t = blockIdx.x;
    int ti = 0;
    #pragma unroll
    for (int ii = 1; ii < 8; ii++) if (t >= ii * (ii + 1) / 2) ti = ii;
    const int tj = t - ti * (ti + 1) / 2;
    const int d0 = ti * 128;
    const int e0 = tj * 128;
    const bool offdiag = (ti != tj);

    const int tid = threadIdx.x;
    const int lane = tid & 31, wid = tid >> 5;
    const int wm = (wid >> 2) * 64;
    const int wn = (wid & 3) * 32;
    const int g = lane >> 2, tig = lane & 3;

    uint32_t sbase = smem_u32(dsm);
    uint32_t aB = sbase, bB = sbase + (unsigned)(3 * HB_STG) * 4;
    const unsigned* Bsm = dsm + 3 * HB_STG;

    float acc[4][4][4];
    #pragma unroll
    for (int i = 0; i < 4; i++)
        #pragma unroll
        for (int j = 0; j < 4; j++)
            #pragma unroll
            for (int k = 0; k < 4; k++) acc[i][j][k] = 0.f;

    h_issue(A, aB, bB, 0, 0, d0, e0, tid);
    h_issue(A, aB, bB, 1, HKT, d0, e0, tid);

    int cur = 0, nxt = 2;
    const int NT = Sn / HKT;   // 128
    for (int tt = 0; tt < NT; tt++) {
        CP_WAIT1();
        __syncthreads();
        if (tt + 2 < NT) h_issue(A, aB, bB, nxt, (tt + 2) * HKT, d0, e0, tid);
        else CP_COMMIT();

        const unsigned* Ast = dsm + cur * HB_STG;
        const unsigned* Bst = Bsm + cur * HB_STG;
        #pragma unroll
        for (int kb = 0; kb < HKT; kb += 8) {
            unsigned afr[4][4], bfr[4][2];
            #pragma unroll
            for (int am = 0; am < 4; am++) {
                int m = wm + am * 16 + g;
                afr[am][0] = Ast[(kb + tig) * BSP + m];
                afr[am][1] = Ast[(kb + tig) * BSP + m + 8];
                afr[am][2] = Ast[(kb + tig + 4) * BSP + m];
                afr[am][3] = Ast[(kb + tig + 4) * BSP + m + 8];
            }
            #pragma unroll
            for (int an = 0; an < 4; an++) {
                int n = wn + an * 8 + g;
                bfr[an][0] = Bst[(kb + tig) * BSP + n];
                bfr[an][1] = Bst[(kb + tig + 4) * BSP + n];
            }
            #pragma unroll
            for (int am = 0; am < 4; am++)
                #pragma unroll
                for (int an = 0; an < 4; an++)
                    mma8(acc[am][an], afr[am], bfr[an]);
        }
        cur = (cur == 2) ? 0 : cur + 1;
        nxt = (nxt == 2) ? 0 : nxt + 1;
    }

    // scale = 1/(S*rms^2): rms from fused sumsq (completed before this kernel)
    float ms = fmaxf(g_scal[0] * (1.0f / 8388608.0f), 1e-12f);
    float rms = fmaxf(sqrtf(ms), 1e-3f);
    const float sc = (1.0f / (float)Sn) / (rms * rms);

    float dsum = 0.f, psum = 0.f;
    #pragma unroll
    for (int am = 0; am < 4; am++) {
        #pragma unroll
        for (int half = 0; half < 2; half++) {
            int row = d0 + wm + am * 16 + g + half * 8;
            #pragma unroll
            for (int an = 0; an < 4; an++) {
                int col = e0 + wn + an * 8 + 2 * tig;
                size_t idx = (size_t)row * Dn + col;
                float h0 = acc[am][an][half * 2 + 0] * sc;
                float h1 = acc[am][an][half * 2 + 1] * sc;
                float2 hp = *(const float2*)&Hp[idx];
                if (LAYER == 0) *(float2*)&H[idx] = make_float2(h0, h1);
                float e0f = h0 - hp.x, e1f = h1 - hp.y;
                dsum += e0f * e0f + e1f * e1f;
                psum += hp.x * hp.x + hp.y * hp.y;
                if (offdiag) {
                    size_t ti0 = (size_t)col * Dn + row;
                    size_t ti1 = (size_t)(col + 1) * Dn + row;
                    float hpa = Hp[ti0], hpb = Hp[ti1];
                    if (LAYER == 0) { H[ti0] = h0; H[ti1] = h1; }
                    float m0f = h0 - hpa, m1f = h1 - hpb;
                    dsum += m0f * m0f + m1f * m1f;
                    psum += hpa * hpa + hpb * hpb;
                } else {
                    if (row == col) {
                        atomicMax((int*)&g_scal[12 + batch], __float_as_int(h0));
                        atomicMin((int*)&g_scal[16 + batch], __float_as_int(h0));
                    } else if (row == col + 1) {
                        atomicMax((int*)&g_scal[12 + batch], __float_as_int(h1));
                        atomicMin((int*)&g_scal[16 + batch], __float_as_int(h1));
                    }
                }
            }
        }
    }
    #pragma unroll
    for (int o = 16; o > 0; o >>= 1) {
        dsum += __shfl_xor_sync(0xffffffffu, dsum, o);
        psum += __shfl_xor_sync(0xffffffffu, psum, o);
    }
    if (lane == 0) {
        atomicAdd(&g_scal[4 + batch], dsum);
        atomicAdd(&g_scal[8 + batch], psum);
    }

    // fused flags: last CTA of the grid computes per-batch complex scales
    __syncthreads();
    if (tid == 0) {
        __threadfence();
        int old = atomicAdd(&g_ctr, 1);
        if (old == 36 * Bn - 1) {
            g_ctr = 0;
            #pragma unroll
            for (int b = 0; b < Bn; b++) {
                float diffn = sqrtf(g_scal[4 + b]);
                float prevn = sqrtf(g_scal[8 + b]);
                float Kv = diffn / (prevn + 1e-6f);
                float dmax = g_scal[12 + b], dmin = g_scal[16 + b];
                float cond = dmax / (dmin + 1e-12f);
                float cr = (Kv > kth[LAYER]) ? js[LAYER] : 1.0f;
                float ci = 0.0f;
                if (cond > COND_TH) {
                    float sn, cs;
                    sincosf(theta[LAYER], &sn, &cs);
                    ci = cr * sn; cr = cr * cs;
                }
                g_scal[20 + b] = cr; g_scal[24 + b] = ci;
                g_scal[4 + b] = 0.f; g_scal[8 + b] = 0.f;
                g_scal[12 + b] = 0.f; g_scal[16 + b] = __int_as_float(0x7f800000);
            }
            g_scal[0] = 0.f;
        }
    }
}

// ---------------- residual update: psi += dampf * delta * c_b (rms cancels) -------
template <int LAYER>
__global__ void k_update(float* __restrict__ out,
                         const float* __restrict__ xr, const float* __restrict__ xi)
{
    int i = blockIdx.x * 256 + threadIdx.x;   // BSD/4
    int m = i >> 8, dq = i & 255;
    int batch = m >> 11;
    float cr = g_scal[20 + batch], ci = g_scal[24 + batch];
    size_t tidx = (size_t)m * Dn + dq * 4;
    float4 t1 = *(const float4*)&g_T[tidx];
    float4 t2 = *(const float4*)&g_T[BSD + tidx];
    float4 t3 = *(const float4*)&g_T[2 * (size_t)BSD + tidx];
    float4 f  = *(const float4*)&g_dampf[LAYER * Dn + dq * 4];
    float4 pr, pi;
    if (LAYER == 0) {
        pr = *(const float4*)&xr[tidx];
        pi = *(const float4*)&xi[tidx];
    } else {
        pr = *(const float4*)&g_psi[tidx];
        pi = *(const float4*)&g_psi[BSD + tidx];
    }

    {
        float re = t1.x - t2.x, im = t3.x - t1.x - t2.x;
        pr.x += f.x * (re * cr - im * ci);  pi.x += f.x * (re * ci + im * cr);
    }
    { float re = t1.y - t2.y, im = t3.y - t1.y - t2.y;
      pr.y += f.y * (re * cr - im * ci);  pi.y += f.y * (re * ci + im * cr); }
    { float re = t1.z - t2.z, im = t3.z - t1.z - t2.z;
      pr.z += f.z * (re * cr - im * ci);  pi.z += f.z * (re * ci + im * cr); }
    { float re = t1.w - t2.w, im = t3.w - t1.w - t2.w;
      pr.w += f.w * (re * cr - im * ci);  pi.w += f.w * (re * ci + im * cr); }

    if (LAYER == 1) {
        *(float4*)&out[tidx]       = pr;
        *(float4*)&out[BSD + tidx] = pi;
    } else {
        *(float4*)&g_psi[tidx]       = pr;
        *(float4*)&g_psi[BSD + tidx] = pi;
        float4 a, b, c;
        a.x = f2tf_f(pr.x); a.y = f2tf_f(pr.y); a.z = f2tf_f(pr.z); a.w = f2tf_f(pr.w);
        b.x = f2tf_f(pi.x); b.y = f2tf_f(pi.y); b.z = f2tf_f(pi.z); b.w = f2tf_f(pi.w);
        c.x = f2tf_f(pr.x + pi.x); c.y = f2tf_f(pr.y + pi.y);
        c.z = f2tf_f(pr.z + pi.z); c.w = f2tf_f(pr.w + pi.w);
        *(float4*)&g_xt0[tidx] = a;
        *(float4*)&g_xt1[tidx] = b;
        *(float4*)&g_am[tidx]  = c;
    }
}

// ---------------- launch ----------------
extern "C" void kernel_launch(void* const* d_in, const int* in_sizes, int n_in,
                              void* d_out, int out_size)
{
    const float* x_real = (const float*)d_in[0];
    const float* x_imag = (const float*)d_in[1];
    const float* H_prev = (const float*)d_in[2];
    const float* W_real = (const float*)d_in[3];
    const float* W_imag = (const float*)d_in[4];
    const float* L_ops  = (const float*)d_in[5];
    const float* theta  = (const float*)d_in[6];
    const float* jscale = (const float*)d_in[7];
    const float* kth    = (const float*)d_in[8];
    float* out = (float*)d_out;

    cudaFuncSetAttribute(k_gemmT, cudaFuncAttributeMaxDynamicSharedMemorySize, GEMM_DYN);
    cudaFuncSetAttribute(k_H<0>,  cudaFuncAttributeMaxDynamicSharedMemorySize, H_DYN);
    cudaFuncSetAttribute(k_H<1>,  cudaFuncAttributeMaxDynamicSharedMemorySize, H_DYN);

    // prep
    k_buildB3<<<(2 * Dn * Dn) / 256, 256>>>(W_real, W_imag);
    k_damp<<<8, 256>>>(L_ops);
    k_init_scal<<<1, 32>>>();
    k_prep<<<(BSD / 4) / 256, 256>>>(x_real, x_imag);

    dim3 gemm_grid(Dn / 128, Mrows / 128, 3);  // (8, 64, 3)
    dim3 H_grid(36, 1, Bn);                    // lower-triangle tiles
    const int ew_blocks = (BSD / 4) / 256;     // 8192

    // layer 0
    k_gemmT<<<gemm_grid, 256, GEMM_DYN>>>(0);
    k_magsum<<<ew_blocks, 256>>>(0);
    k_H<0><<<H_grid, 256, H_DYN>>>(H_prev, theta, jscale, kth);
    k_update<0><<<ew_blocks, 256>>>(out, x_real, x_imag);

    // layer 1
    k_gemmT<<<gemm_grid, 256, GEMM_DYN>>>(1);
    k_magsum<<<ew_blocks, 256>>>(1);
    k_H<1><<<H_grid, 256, H_DYN>>>(H_prev, theta, jscale, kth);
    k_update<1><<<ew_blocks, 256>>>(out, x_real, x_imag);
}

// round 17
// speedup vs baseline: 1.7812x; 1.0189x over previous
#include <cuda_runtime.h>
#include <math.h>
#include <stdint.h>

// Problem constants
#define Bn   4
#define Sn   2048
#define Dn   1024
#define Mrows 8192
#define K2   2048
#define BSD  8388608
#define GAMMA 0.01f
#define COND_TH 100.0f

// T-GEMM tiling (KT=32)
#define KT   32
#define ASP  36                 // A smem row: 32 data + 4 pad floats (144B, 16B-aligned)
#define BSP  136                // B smem row stride (8 mod 32 -> conflict-free)
#define A_STG (128*ASP)         // 4608 floats per A stage
#define B_STG (KT*BSP)          // 4352 floats per B stage
#define GEMM_DYN (3*(A_STG+B_STG)*4)   // 107520 B

// H tiling (KT=32)
#define HKT  32
#define HB_STG (HKT*BSP)        // 4352 floats per stage
#define H_DYN (3*2*HB_STG*4)    // 104448 B

// ---------------- scratch (device globals; allocation-free) ----------------
__device__ float g_psi[2 * BSD];   // unrounded psi after layer 0: [0..BSD) re, [BSD..) im
__device__ float g_xt0[BSD];       // tf32(x_re), then tf32(psi_re)
__device__ float g_xt1[BSD];       // tf32(x_im), then tf32(psi_im)
__device__ float g_am [BSD];       // tf32(a3), then mag' (unscaled)
__device__ float g_T  [3 * BSD];   // T1, T2, T3
__device__ float g_B3 [2 * 3 * Dn * Dn];  // per layer: B1=Wr-I, B2=Wi, B3 (tf32-rounded)
__device__ float g_H  [Bn * Dn * Dn];     // layer-0 H only
__device__ float g_dampf[2 * Dn];
// [0]=sumsq, [4..7]=diffsq[b], [8..11]=prevsq[b],
// [12..15]=dmax[b], [16..19]=dmin[b], [20..23]=cr[b], [24..27]=ci[b]
__device__ float g_scal[32];
__device__ int   g_ctr;            // last-CTA counter for fused flags

__device__ __forceinline__ unsigned f2tf(float f)
{
    unsigned r;
    asm("cvt.rna.tf32.f32 %0, %1;" : "=r"(r) : "f"(f));
    return r;
}
__device__ __forceinline__ float f2tf_f(float f) { unsigned r = f2tf(f); return __uint_as_float(r); }

__device__ __forceinline__ void mma8(float* c, const unsigned* a, const unsigned* b)
{
    asm("mma.sync.aligned.m16n8k8.row.col.f32.tf32.tf32.f32 "
        "{%0,%1,%2,%3}, {%4,%5,%6,%7}, {%8,%9}, {%0,%1,%2,%3};"
        : "+f"(c[0]), "+f"(c[1]), "+f"(c[2]), "+f"(c[3])
        : "r"(a[0]), "r"(a[1]), "r"(a[2]), "r"(a[3]), "r"(b[0]), "r"(b[1]));
}

__device__ __forceinline__ uint32_t smem_u32(const void* p)
{
    uint32_t a;
    asm("{ .reg .u64 t; cvta.to.shared.u64 t, %1; cvt.u32.u64 %0, t; }" : "=r"(a) : "l"(p));
    return a;
}
__device__ __forceinline__ void cpa16(uint32_t dst, const void* src)
{
    asm volatile("cp.async.cg.shared.global [%0], [%1], 16;" :: "r"(dst), "l"(src));
}
#define CP_COMMIT() asm volatile("cp.async.commit_group;")
#define CP_WAIT1()  asm volatile("cp.async.wait_group 1;")

// ---------------- prep kernels ----------------
__global__ void k_buildB3(const float* __restrict__ Wr, const float* __restrict__ Wi)
{
    int i = blockIdx.x * 256 + threadIdx.x;       // 2 * 1024 * 1024
    int l = i >> 20;
    int kn = i & 1048575;
    int k = kn >> 10, n = kn & 1023;
    size_t WL = (size_t)l * Dn * Dn + kn;
    float b1 = Wr[WL] - (k == n ? 1.0f : 0.0f);
    float b2 = Wi[WL];
    size_t base = (size_t)l * 3 * Dn * Dn + kn;
    g_B3[base]               = f2tf_f(b1);
    g_B3[base + Dn * Dn]     = f2tf_f(b2);
    g_B3[base + 2 * Dn * Dn] = f2tf_f(b1 + b2);
}

// damp + scalar init fused
__global__ void k_damp(const float* __restrict__ L)
{
    int t = blockIdx.x * 256 + threadIdx.x;   // 2048
    if (t < 2 * Dn) {
        int l = t >> 10, d = t & 1023;
        float s = 0.f;
        #pragma unroll
        for (int k = 0; k < 4; k++) { float v = L[l * 4096 + k * Dn + d]; s += v * v; }
        g_dampf[t] = 1.0f - GAMMA * s;
    }
    if (blockIdx.x == 0) {
        if (threadIdx.x < 32)
            g_scal[threadIdx.x] = (threadIdx.x >= 16 && threadIdx.x < 20)
                                ? __int_as_float(0x7f800000) : 0.0f;
        if (threadIdx.x == 32) g_ctr = 0;
    }
}

// xt0 = tf32(xr), xt1 = tf32(xi), a3 = tf32(xr+xi)
__global__ void k_prep(const float* __restrict__ xr, const float* __restrict__ xi)
{
    int i = blockIdx.x * 256 + threadIdx.x;   // BSD/4
    size_t idx = (size_t)i * 4;
    float4 r = *(const float4*)&xr[idx];
    float4 im = *(const float4*)&xi[idx];
    float4 a, b, c;
    a.x = f2tf_f(r.x);  a.y = f2tf_f(r.y);  a.z = f2tf_f(r.z);  a.w = f2tf_f(r.w);
    b.x = f2tf_f(im.x); b.y = f2tf_f(im.y); b.z = f2tf_f(im.z); b.w = f2tf_f(im.w);
    c.x = f2tf_f(r.x + im.x); c.y = f2tf_f(r.y + im.y);
    c.z = f2tf_f(r.z + im.z); c.w = f2tf_f(r.w + im.w);
    *(float4*)&g_xt0[idx] = a;
    *(float4*)&g_xt1[idx] = b;
    *(float4*)&g_am[idx]  = c;
}

// ---------------- Karatsuba T GEMMs: cp.async 3-stage pipeline, KT=32 -------------
__device__ __forceinline__ void gemm_issue(const float* __restrict__ A,
                                           const float* __restrict__ Bm,
                                           uint32_t aB, uint32_t bB,
                                           int s, int kt, int m0, int n0, int tid)
{
    #pragma unroll
    for (int u = 0; u < 4; u++) {
        int c = tid + u * 256;
        int row = c >> 3, q = c & 7;
        cpa16(aB + (unsigned)(s * A_STG + row * ASP + q * 4) * 4,
              A + (size_t)(m0 + row) * Dn + kt + q * 4);
    }
    #pragma unroll
    for (int u = 0; u < 4; u++) {
        int c = tid + u * 256;
        int row = c >> 5, q = c & 31;
        cpa16(bB + (unsigned)(s * B_STG + row * BSP + q * 4) * 4,
              Bm + (size_t)(kt + row) * Dn + n0 + q * 4);
    }
    CP_COMMIT();
}

__global__ __launch_bounds__(256, 2) void k_gemmT(int layer)
{
    extern __shared__ unsigned dsm[];
    const int z = blockIdx.z;
    const float* __restrict__ A = (z == 0) ? g_xt0 : (z == 1) ? g_xt1 : g_am;
    const float* __restrict__ Bm = g_B3 + ((size_t)layer * 3 + z) * Dn * Dn;
    float* __restrict__ C = g_T + (size_t)z * BSD;

    const int tid = threadIdx.x;
    const int m0 = blockIdx.y * 128;
    const int n0 = blockIdx.x * 128;
    const int lane = tid & 31, wid = tid >> 5;
    const int wm = (wid >> 2) * 64;
    const int wn = (wid & 3) * 32;
    const int g = lane >> 2, tig = lane & 3;

    uint32_t sbase = smem_u32(dsm);
    uint32_t aB = sbase, bB = sbase + (unsigned)(3 * A_STG) * 4;
    const unsigned* Bsm = dsm + 3 * A_STG;

    float acc[4][4][4];
    #pragma unroll
    for (int i = 0; i < 4; i++)
        #pragma unroll
        for (int j = 0; j < 4; j++)
            #pragma unroll
            for (int k = 0; k < 4; k++) acc[i][j][k] = 0.f;

    gemm_issue(A, Bm, aB, bB, 0, 0, m0, n0, tid);
    gemm_issue(A, Bm, aB, bB, 1, KT, m0, n0, tid);

    int cur = 0, nxt = 2;
    const int NT = Dn / KT;   // 32
    for (int t = 0; t < NT; t++) {
        CP_WAIT1();
        __syncthreads();
        if (t + 2 < NT) gemm_issue(A, Bm, aB, bB, nxt, (t + 2) * KT, m0, n0, tid);
        else CP_COMMIT();

        const unsigned* Ast = dsm + cur * A_STG;
        const unsigned* Bst = Bsm + cur * B_STG;
        #pragma unroll
        for (int kb = 0; kb < KT; kb += 8) {
            unsigned afr[4][4], bfr[4][2];
            #pragma unroll
            for (int am = 0; am < 4; am++) {
                int mrow = (wm + am * 16 + g) * ASP;
                afr[am][0] = Ast[mrow + kb + tig];
                afr[am][1] = Ast[mrow + 8 * ASP + kb + tig];
                afr[am][2] = Ast[mrow + kb + tig + 4];
                afr[am][3] = Ast[mrow + 8 * ASP + kb + tig + 4];
            }
            #pragma unroll
            for (int an = 0; an < 4; an++) {
                int n = wn + an * 8 + g;
                bfr[an][0] = Bst[(kb + tig) * BSP + n];
                bfr[an][1] = Bst[(kb + tig + 4) * BSP + n];
            }
            #pragma unroll
            for (int am = 0; am < 4; am++)
                #pragma unroll
                for (int an = 0; an < 4; an++)
                    mma8(acc[am][an], afr[am], bfr[an]);
        }
        cur = (cur == 2) ? 0 : cur + 1;
        nxt = (nxt == 2) ? 0 : nxt + 1;
    }

    #pragma unroll
    for (int am = 0; am < 4; am++) {
        int r0 = m0 + wm + am * 16 + g;
        #pragma unroll
        for (int an = 0; an < 4; an++) {
            int c0 = n0 + wn + an * 8 + 2 * tig;
            *(float2*)&C[(size_t)r0 * Dn + c0]       = make_float2(acc[am][an][0], acc[am][an][1]);
            *(float2*)&C[(size_t)(r0 + 8) * Dn + c0] = make_float2(acc[am][an][2], acc[am][an][3]);
        }
    }
}

// ---------------- fused: mag' = tf32(|delta|*|dampf|) (unscaled) + sumsq(delta) ----
__global__ void k_magsum(int layer)
{
    __shared__ float red[8];
    int i = blockIdx.x * 256 + threadIdx.x;   // BSD/4
    int m = i >> 8, dq = i & 255;
    size_t idx = (size_t)m * Dn + dq * 4;
    float4 t1 = *(const float4*)&g_T[idx];
    float4 t2 = *(const float4*)&g_T[BSD + idx];
    float4 t3 = *(const float4*)&g_T[2 * (size_t)BSD + idx];
    float4 f  = *(const float4*)&g_dampf[layer * Dn + dq * 4];
    float s = 0.f;
    float4 o;
    { float re = t1.x - t2.x, im = t3.x - t1.x - t2.x; float q = re * re + im * im; s += q;
      o.x = f2tf_f(sqrtf(q) * fabsf(f.x)); }
    { float re = t1.y - t2.y, im = t3.y - t1.y - t2.y; float q = re * re + im * im; s += q;
      o.y = f2tf_f(sqrtf(q) * fabsf(f.y)); }
    { float re = t1.z - t2.z, im = t3.z - t1.z - t2.z; float q = re * re + im * im; s += q;
      o.z = f2tf_f(sqrtf(q) * fabsf(f.z)); }
    { float re = t1.w - t2.w, im = t3.w - t1.w - t2.w; float q = re * re + im * im; s += q;
      o.w = f2tf_f(sqrtf(q) * fabsf(f.w)); }
    *(float4*)&g_am[idx] = o;
    #pragma unroll
    for (int o2 = 16; o2 > 0; o2 >>= 1) s += __shfl_xor_sync(0xffffffffu, s, o2);
    int lane = threadIdx.x & 31, w = threadIdx.x >> 5;
    if (lane == 0) red[w] = s;
    __syncthreads();
    if (w == 0) {
        s = (lane < 8) ? red[lane] : 0.f;
        #pragma unroll
        for (int o2 = 4; o2 > 0; o2 >>= 1) s += __shfl_xor_sync(0xffffffffu, s, o2);
        if (lane == 0) atomicAdd(&g_scal[0], s);
    }
}

// ---------------- H = mag'^T mag' /(S*rms^2): cp.async 3-stage KT=32, triangular,
//                  diag-tile load dedup, fused per-batch flags in last CTA --------
__device__ __forceinline__ void h_issue(const float* __restrict__ A,
                                        uint32_t aB, uint32_t bB,
                                        int s, int kt, int d0, int e0, int tid,
                                        bool diag)
{
    #pragma unroll
    for (int u = 0; u < 4; u++) {
        int c = tid + u * 256;
        int row = c >> 5, q = c & 31;
        cpa16(aB + (unsigned)(s * HB_STG + row * BSP + q * 4) * 4,
              A + (size_t)(kt + row) * Dn + d0 + q * 4);
        if (!diag)
            cpa16(bB + (unsigned)(s * HB_STG + row * BSP + q * 4) * 4,
                  A + (size_t)(kt + row) * Dn + e0 + q * 4);
    }
    CP_COMMIT();
}

template <int LAYER>
__global__ __launch_bounds__(256, 2) void k_H(const float* __restrict__ Hprev_in,
                                              const float* __restrict__ theta,
                                              const float* __restrict__ js,
                                              const float* __restrict__ kth)
{
    extern __shared__ unsigned dsm[];
    const int batch = blockIdx.z;
    const float* __restrict__ A = g_am + (size_t)batch * Sn * Dn;
    float* __restrict__ H = g_H + (size_t)batch * Dn * Dn;
    const float* __restrict__ Hp = (LAYER == 0)
        ? (Hprev_in + (size_t)batch * Dn * Dn)
        : (g_H + (size_t)batch * Dn * Dn);

    const int t = blockIdx.x;
    int ti = 0;
    #pragma unroll
    for (int ii = 1; ii < 8; ii++) if (t >= ii * (ii + 1) / 2) ti = ii;
    const int tj = t - ti * (ti + 1) / 2;
    const int d0 = ti * 128;
    const int e0 = tj * 128;
    const bool offdiag = (ti != tj);

    const int tid = threadIdx.x;
    const int lane = tid & 31, wid = tid >> 5;
    const int wm = (wid >> 2) * 64;
    const int wn = (wid & 3) * 32;
    const int g = lane >> 2, tig = lane & 3;

    uint32_t sbase = smem_u32(dsm);
    uint32_t aB = sbase, bB = sbase + (unsigned)(3 * HB_STG) * 4;
    // diag tiles read B fragments from the A stages (identical data, loaded once)
    const unsigned* Bsm = offdiag ? (dsm + 3 * HB_STG) : dsm;

    float acc[4][4][4];
    #pragma unroll
    for (int i = 0; i < 4; i++)
        #pragma unroll
        for (int j = 0; j < 4; j++)
            #pragma unroll
            for (int k = 0; k < 4; k++) acc[i][j][k] = 0.f;

    h_issue(A, aB, bB, 0, 0, d0, e0, tid, !offdiag);
    h_issue(A, aB, bB, 1, HKT, d0, e0, tid, !offdiag);

    int cur = 0, nxt = 2;
    const int NT = Sn / HKT;   // 64
    for (int tt = 0; tt < NT; tt++) {
        CP_WAIT1();
        __syncthreads();
        if (tt + 2 < NT) h_issue(A, aB, bB, nxt, (tt + 2) * HKT, d0, e0, tid, !offdiag);
        else CP_COMMIT();

        const unsigned* Ast = dsm + cur * HB_STG;
        const unsigned* Bst = Bsm + cur * HB_STG;
        #pragma unroll
        for (int kb = 0; kb < HKT; kb += 8) {
            unsigned afr[4][4], bfr[4][2];
            #pragma unroll
            for (int am = 0; am < 4; am++) {
                int m = wm + am * 16 + g;
                afr[am][0] = Ast[(kb + tig) * BSP + m];
                afr[am][1] = Ast[(kb + tig) * BSP + m + 8];
                afr[am][2] = Ast[(kb + tig + 4) * BSP + m];
                afr[am][3] = Ast[(kb + tig + 4) * BSP + m + 8];
            }
            #pragma unroll
            for (int an = 0; an < 4; an++) {
                int n = wn + an * 8 + g;
                bfr[an][0] = Bst[(kb + tig) * BSP + n];
                bfr[an][1] = Bst[(kb + tig + 4) * BSP + n];
            }
            #pragma unroll
            for (int am = 0; am < 4; am++)
                #pragma unroll
                for (int an = 0; an < 4; an++)
                    mma8(acc[am][an], afr[am], bfr[an]);
        }
        cur = (cur == 2) ? 0 : cur + 1;
        nxt = (nxt == 2) ? 0 : nxt + 1;
    }

    // scale = 1/(S*rms^2): rms from fused sumsq (completed before this kernel)
    float ms = fmaxf(g_scal[0] * (1.0f / 8388608.0f), 1e-12f);
    float rms = fmaxf(sqrtf(ms), 1e-3f);
    const float sc = (1.0f / (float)Sn) / (rms * rms);

    float dsum = 0.f, psum = 0.f;
    #pragma unroll
    for (int am = 0; am < 4; am++) {
        #pragma unroll
        for (int half = 0; half < 2; half++) {
            int row = d0 + wm + am * 16 + g + half * 8;
            #pragma unroll
            for (int an = 0; an < 4; an++) {
                int col = e0 + wn + an * 8 + 2 * tig;
                size_t idx = (size_t)row * Dn + col;
                float h0 = acc[am][an][half * 2 + 0] * sc;
                float h1 = acc[am][an][half * 2 + 1] * sc;
                float2 hp = *(const float2*)&Hp[idx];
                if (LAYER == 0) *(float2*)&H[idx] = make_float2(h0, h1);
                float e0f = h0 - hp.x, e1f = h1 - hp.y;
                dsum += e0f * e0f + e1f * e1f;
                psum += hp.x * hp.x + hp.y * hp.y;
                if (offdiag) {
                    size_t ti0 = (size_t)col * Dn + row;
                    size_t ti1 = (size_t)(col + 1) * Dn + row;
                    float hpa = Hp[ti0], hpb = Hp[ti1];
                    if (LAYER == 0) { H[ti0] = h0; H[ti1] = h1; }
                    float m0f = h0 - hpa, m1f = h1 - hpb;
                    dsum += m0f * m0f + m1f * m1f;
                    psum += hpa * hpa + hpb * hpb;
                } else {
                    if (row == col) {
                        atomicMax((int*)&g_scal[12 + batch], __float_as_int(h0));
                        atomicMin((int*)&g_scal[16 + batch], __float_as_int(h0));
                    } else if (row == col + 1) {
                        atomicMax((int*)&g_scal[12 + batch], __float_as_int(h1));
                        atomicMin((int*)&g_scal[16 + batch], __float_as_int(h1));
                    }
                }
            }
        }
    }
    #pragma unroll
    for (int o = 16; o > 0; o >>= 1) {
        dsum += __shfl_xor_sync(0xffffffffu, dsum, o);
        psum += __shfl_xor_sync(0xffffffffu, psum, o);
    }
    if (lane == 0) {
        atomicAdd(&g_scal[4 + batch], dsum);
        atomicAdd(&g_scal[8 + batch], psum);
    }

    // fused flags: last CTA of the grid computes per-batch complex scales
    __syncthreads();
    if (tid == 0) {
        __threadfence();
        int old = atomicAdd(&g_ctr, 1);
        if (old == 36 * Bn - 1) {
            g_ctr = 0;
            #pragma unroll
            for (int b = 0; b < Bn; b++) {
                float diffn = sqrtf(g_scal[4 + b]);
                float prevn = sqrtf(g_scal[8 + b]);
                float Kv = diffn / (prevn + 1e-6f);
                float dmax = g_scal[12 + b], dmin = g_scal[16 + b];
                float cond = dmax / (dmin + 1e-12f);
                float cr = (Kv > kth[LAYER]) ? js[LAYER] : 1.0f;
                float ci = 0.0f;
                if (cond > COND_TH) {
                    float sn, cs;
                    sincosf(theta[LAYER], &sn, &cs);
                    ci = cr * sn; cr = cr * cs;
                }
                g_scal[20 + b] = cr; g_scal[24 + b] = ci;
                g_scal[4 + b] = 0.f; g_scal[8 + b] = 0.f;
                g_scal[12 + b] = 0.f; g_scal[16 + b] = __int_as_float(0x7f800000);
            }
            g_scal[0] = 0.f;
        }
    }
}

// ---------------- residual update: psi += dampf * delta * c_b (rms cancels) -------
template <int LAYER>
__global__ void k_update(float* __restrict__ out,
                         const float* __restrict__ xr, const float* __restrict__ xi)
{
    int i = blockIdx.x * 256 + threadIdx.x;   // BSD/4
    int m = i >> 8, dq = i & 255;
    int batch = m >> 11;
    float cr = g_scal[20 + batch], ci = g_scal[24 + batch];
    size_t tidx = (size_t)m * Dn + dq * 4;
    float4 t1 = *(const float4*)&g_T[tidx];
    float4 t2 = *(const float4*)&g_T[BSD + tidx];
    float4 t3 = *(const float4*)&g_T[2 * (size_t)BSD + tidx];
    float4 f  = *(const float4*)&g_dampf[LAYER * Dn + dq * 4];
    float4 pr, pi;
    if (LAYER == 0) {
        pr = *(const float4*)&xr[tidx];
        pi = *(const float4*)&xi[tidx];
    } else {
        pr = *(const float4*)&g_psi[tidx];
        pi = *(const float4*)&g_psi[BSD + tidx];
    }

    {
        float re = t1.x - t2.x, im = t3.x - t1.x - t2.x;
        pr.x += f.x * (re * cr - im * ci);  pi.x += f.x * (re * ci + im * cr);
    }
    { float re = t1.y - t2.y, im = t3.y - t1.y - t2.y;
      pr.y += f.y * (re * cr - im * ci);  pi.y += f.y * (re * ci + im * cr); }
    { float re = t1.z - t2.z, im = t3.z - t1.z - t2.z;
      pr.z += f.z * (re * cr - im * ci);  pi.z += f.z * (re * ci + im * cr); }
    { float re = t1.w - t2.w, im = t3.w - t1.w - t2.w;
      pr.w += f.w * (re * cr - im * ci);  pi.w += f.w * (re * ci + im * cr); }

    if (LAYER == 1) {
        *(float4*)&out[tidx]       = pr;
        *(float4*)&out[BSD + tidx] = pi;
    } else {
        *(float4*)&g_psi[tidx]       = pr;
        *(float4*)&g_psi[BSD + tidx] = pi;
        float4 a, b, c;
        a.x = f2tf_f(pr.x); a.y = f2tf_f(pr.y); a.z = f2tf_f(pr.z); a.w = f2tf_f(pr.w);
        b.x = f2tf_f(pi.x); b.y = f2tf_f(pi.y); b.z = f2tf_f(pi.z); b.w = f2tf_f(pi.w);
        c.x = f2tf_f(pr.x + pi.x); c.y = f2tf_f(pr.y + pi.y);
        c.z = f2tf_f(pr.z + pi.z); c.w = f2tf_f(pr.w + pi.w);
        *(float4*)&g_xt0[tidx] = a;
        *(float4*)&g_xt1[tidx] = b;
        *(float4*)&g_am[tidx]  = c;
    }
}

// ---------------- launch ----------------
extern "C" void kernel_launch(void* const* d_in, const int* in_sizes, int n_in,
                              void* d_out, int out_size)
{
    const float* x_real = (const float*)d_in[0];
    const float* x_imag = (const float*)d_in[1];
    const float* H_prev = (const float*)d_in[2];
    const float* W_real = (const float*)d_in[3];
    const float* W_imag = (const float*)d_in[4];
    const float* L_ops  = (const float*)d_in[5];
    const float* theta  = (const float*)d_in[6];
    const float* jscale = (const float*)d_in[7];
    const float* kth    = (const float*)d_in[8];
    float* out = (float*)d_out;

    cudaFuncSetAttribute(k_gemmT, cudaFuncAttributeMaxDynamicSharedMemorySize, GEMM_DYN);
    cudaFuncSetAttribute(k_H<0>,  cudaFuncAttributeMaxDynamicSharedMemorySize, H_DYN);
    cudaFuncSetAttribute(k_H<1>,  cudaFuncAttributeMaxDynamicSharedMemorySize, H_DYN);

    // prep
    k_buildB3<<<(2 * Dn * Dn) / 256, 256>>>(W_real, W_imag);
    k_damp<<<8, 256>>>(L_ops);
    k_prep<<<(BSD / 4) / 256, 256>>>(x_real, x_imag);

    dim3 gemm_grid(Dn / 128, Mrows / 128, 3);  // (8, 64, 3)
    dim3 H_grid(36, 1, Bn);                    // lower-triangle tiles
    const int ew_blocks = (BSD / 4) / 256;     // 8192

    // layer 0
    k_gemmT<<<gemm_grid, 256, GEMM_DYN>>>(0);
    k_magsum<<<ew_blocks, 256>>>(0);
    k_H<0><<<H_grid, 256, H_DYN>>>(H_prev, theta, jscale, kth);
    k_update<0><<<ew_blocks, 256>>>(out, x_real, x_imag);

    // layer 1
    k_gemmT<<<gemm_grid, 256, GEMM_DYN>>>(1);
    k_magsum<<<ew_blocks, 256>>>(1);
    k_H<1><<<H_grid, 256, H_DYN>>>(H_prev, theta, jscale, kth);
    k_update<1><<<ew_blocks, 256>>>(out, x_real, x_imag);
}